// round 14
// baseline (speedup 1.0000x reference)
#include <cuda_runtime.h>
#include <cuda_fp16.h>
#include <cstdint>

// ---------------- problem constants ----------------
#define BB   16
#define SS   512
#define HH   768
#define NH_  12
#define DD   64
#define FF_  3072
#define LL   4
#define MR   (BB*SS)
#define SCALE_Q 0.125f
#define LN_EPS 1e-5f

#define HHxHH   (HH*HH)
#define HHxFF   (HH*FF_)
#define NQKV    (3*HH)                 // 2304
#define QKV_STRIDE ((size_t)MR*HH)
#define NBIAS   ((size_t)BB*NH_*SS*SS)

// ---------------- scratch ----------------
__device__ __align__(16) float  g_h[(size_t)MR*HH];
__device__ __align__(16) __half g_y[(size_t)MR*HH];
__device__ __align__(16) __half g_qkv[(size_t)3*MR*HH];      // q|k|v each [B,NH,S,D]
__device__ __align__(16) __half g_attn[(size_t)MR*HH];       // [B,S,H]
__device__ __align__(16) __half g_ff[(size_t)MR*FF_];
__device__ __align__(16) __half g_bias16[NBIAS];             // fp16 attn_bias
__device__ __align__(16) __half g_w16[(size_t)LL*(4*HHxHH + 2*HHxFF)];
__device__ __align__(16) float  g_bqkv[(size_t)LL*NQKV];

#define OFF_QKV ((size_t)0)
#define OFF_WO  ((size_t)3*LL*HHxHH)
#define OFF_W1  ((size_t)4*LL*HHxHH)
#define OFF_W2  ((size_t)4*LL*HHxHH + (size_t)LL*HHxFF)

// ---------------- init kernels ----------------
#define NPAIRS ((size_t)LL*(4*HHxHH + 2*HHxFF)/2)
#define NCOPY4 ((size_t)MR*HH/4)

__global__ void initw_kernel(
    const float* __restrict__ wq, const float* __restrict__ wk,
    const float* __restrict__ wv, const float* __restrict__ wo,
    const float* __restrict__ w1, const float* __restrict__ w2,
    __half* __restrict__ dst)
{
    const size_t NP = (size_t)LL * HHxHH / 2;
    const size_t NF = (size_t)LL * HHxFF / 2;
    size_t i = (size_t)blockIdx.x * blockDim.x + threadIdx.x;
    if (i >= NPAIRS) return;
    const float* src; size_t off, dpi;
    if (i < 3 * NP) {
        size_t g = i / NP; off = i - g * NP;
        src = (g == 0) ? wq : (g == 1) ? wk : wv;
        size_t l  = off / (HHxHH / 2);
        size_t r  = off - l * (HHxHH / 2);
        size_t k  = r / (HH / 2);
        size_t nc = r - k * (HH / 2);
        dpi = l * ((size_t)HH * NQKV / 2) + k * (NQKV / 2) + g * (HH / 2) + nc;
    } else {
        dpi = i;
        if (i < 4 * NP) { src = wo; off = i - 3 * NP; }
        else {
            size_t j = i - 4 * NP;
            size_t g = j / NF; off = j - g * NF;
            src = g ? w2 : w1;
        }
    }
    float2 f = reinterpret_cast<const float2*>(src)[off];
    reinterpret_cast<__half2*>(dst)[dpi] = __floats2half2_rn(f.x, f.y);
}

__global__ void inith_kernel(const float* __restrict__ x, float* __restrict__ h) {
    size_t i = (size_t)blockIdx.x * blockDim.x + threadIdx.x;
    if (i < NCOPY4)
        reinterpret_cast<float4*>(h)[i] = reinterpret_cast<const float4*>(x)[i];
}

__global__ void initb_kernel(const float* __restrict__ bq, const float* __restrict__ bk,
                             const float* __restrict__ bv, float* __restrict__ dst) {
    int i = blockIdx.x * blockDim.x + threadIdx.x;
    if (i >= LL * NQKV) return;
    int l = i / NQKV, n = i - l * NQKV;
    float v = (n < HH) ? bq[l * HH + n]
            : (n < 2 * HH) ? bk[l * HH + n - HH]
            : bv[l * HH + n - 2 * HH];
    dst[i] = v;
}

__global__ void initab_kernel(const float* __restrict__ src, __half* __restrict__ dst) {
    size_t i = (size_t)blockIdx.x * blockDim.x + threadIdx.x;
    if (i < NBIAS / 2) {
        float2 f = reinterpret_cast<const float2*>(src)[i];
        reinterpret_cast<__half2*>(dst)[i] = __floats2half2_rn(f.x, f.y);
    }
}

// ---------------- LayerNorm: warp-per-row, 8 rows/block ----------------
__global__ __launch_bounds__(256) void ln_kernel(
    const float* __restrict__ in, const float* __restrict__ g, const float* __restrict__ b,
    __half* __restrict__ outH, float* __restrict__ outF)
{
    const int w = threadIdx.x >> 5, lane = threadIdx.x & 31;
    const int row = blockIdx.x * 8 + w;
    const float* x = in + (size_t)row * HH;

    float4 v[6];
    float s = 0.f, s2 = 0.f;
#pragma unroll
    for (int i = 0; i < 6; i++) {
        v[i] = *reinterpret_cast<const float4*>(x + lane * 4 + i * 128);
        s  += v[i].x + v[i].y + v[i].z + v[i].w;
        s2 += v[i].x * v[i].x + v[i].y * v[i].y + v[i].z * v[i].z + v[i].w * v[i].w;
    }
#pragma unroll
    for (int o = 16; o; o >>= 1) {
        s  += __shfl_xor_sync(0xffffffffu, s,  o);
        s2 += __shfl_xor_sync(0xffffffffu, s2, o);
    }
    const float mean = s * (1.f / HH);
    const float rstd = rsqrtf(s2 * (1.f / HH) - mean * mean + LN_EPS);

#pragma unroll
    for (int i = 0; i < 6; i++) {
        const int c = lane * 4 + i * 128;
        float o0 = (v[i].x - mean) * rstd * g[c]     + b[c];
        float o1 = (v[i].y - mean) * rstd * g[c + 1] + b[c + 1];
        float o2 = (v[i].z - mean) * rstd * g[c + 2] + b[c + 2];
        float o3 = (v[i].w - mean) * rstd * g[c + 3] + b[c + 3];
        if (outH) {
            __half2 p0 = __floats2half2_rn(o0, o1);
            __half2 p1 = __floats2half2_rn(o2, o3);
            uint2 pk = { *reinterpret_cast<uint32_t*>(&p0), *reinterpret_cast<uint32_t*>(&p1) };
            *reinterpret_cast<uint2*>(outH + (size_t)row * HH + c) = pk;
        } else {
            float4 ov = { o0, o1, o2, o3 };
            *reinterpret_cast<float4*>(outF + (size_t)row * HH + c) = ov;
        }
    }
}

// ---------------- asm helpers ----------------
__device__ __forceinline__ void cp16(void* smem, const void* gmem) {
    unsigned sa = (unsigned)__cvta_generic_to_shared(smem);
    asm volatile("cp.async.cg.shared.global [%0], [%1], 16;\n" :: "r"(sa), "l"(gmem));
}
__device__ __forceinline__ void cp_commit() { asm volatile("cp.async.commit_group;\n"); }
__device__ __forceinline__ unsigned smem_u32(const void* p) {
    return (unsigned)__cvta_generic_to_shared(p);
}
__device__ __forceinline__ uint32_t h2_as_u32(__half2 h) {
    return *reinterpret_cast<uint32_t*>(&h);
}
__device__ __forceinline__ void ldsm4(uint32_t& r0, uint32_t& r1, uint32_t& r2, uint32_t& r3,
                                      unsigned addr) {
    asm volatile("ldmatrix.sync.aligned.m8n8.x4.shared.b16 {%0,%1,%2,%3}, [%4];"
                 : "=r"(r0), "=r"(r1), "=r"(r2), "=r"(r3) : "r"(addr));
}
__device__ __forceinline__ void ldsm4t(uint32_t& r0, uint32_t& r1, uint32_t& r2, uint32_t& r3,
                                       unsigned addr) {
    asm volatile("ldmatrix.sync.aligned.m8n8.x4.trans.shared.b16 {%0,%1,%2,%3}, [%4];"
                 : "=r"(r0), "=r"(r1), "=r"(r2), "=r"(r3) : "r"(addr));
}
__device__ __forceinline__ void mma16816(float& d0, float& d1, float& d2, float& d3,
                                         uint32_t a0, uint32_t a1, uint32_t a2, uint32_t a3,
                                         uint32_t b0, uint32_t b1) {
    asm volatile(
        "mma.sync.aligned.m16n8k16.row.col.f32.f16.f16.f32 "
        "{%0,%1,%2,%3}, {%4,%5,%6,%7}, {%8,%9}, {%0,%1,%2,%3};"
        : "+f"(d0), "+f"(d1), "+f"(d2), "+f"(d3)
        : "r"(a0), "r"(a1), "r"(a2), "r"(a3), "r"(b0), "r"(b1));
}

// ---------------- flash attention (unchanged) ----------------
__global__ __launch_bounds__(256, 2) void flash_kernel(
    const __half* __restrict__ qg, const __half* __restrict__ kg,
    const __half* __restrict__ vg, const __half* __restrict__ biasg,
    __half* __restrict__ outH)
{
    __shared__ __align__(16) __half Qs[128 * 64];
    __shared__ __align__(16) __half Ks[2][64 * 64];
    __shared__ __align__(16) __half Vs[2][64 * 64];

    const int t = threadIdx.x, w = t >> 5, lane = t & 31;
    const int z = blockIdx.y;
    const int b = z / NH_, hh = z - b * NH_;
    const int q0 = blockIdx.x * 128;

    const __half* Qg = qg + (size_t)z * SS * DD + (size_t)q0 * DD;
    const __half* Kg = kg + (size_t)z * SS * DD;
    const __half* Vg = vg + (size_t)z * SS * DD;
    const __half* Bg = biasg + (size_t)z * SS * SS + (size_t)q0 * SS;

    const unsigned sQ = smem_u32(Qs);
    const unsigned sK[2] = { smem_u32(Ks[0]), smem_u32(Ks[1]) };
    const unsigned sV[2] = { smem_u32(Vs[0]), smem_u32(Vs[1]) };

    auto loadQ = [&]() {
#pragma unroll
        for (int j = 0; j < 4; j++) {
            int idx = t + j * 256;
            int r = idx >> 3, c = idx & 7;
            cp16((char*)Qs + r * 128 + ((c ^ (r & 7)) << 4), Qg + (size_t)r * DD + c * 8);
        }
    };
    auto loadKV = [&](int s, int chunk) {
        const __half* kc = Kg + (size_t)chunk * 64 * DD;
        const __half* vc = Vg + (size_t)chunk * 64 * DD;
#pragma unroll
        for (int j = 0; j < 2; j++) {
            int idx = t + j * 256;
            int r = idx >> 3, c = idx & 7;
            cp16((char*)Ks[s] + r * 128 + ((c ^ (r & 7)) << 4), kc + (size_t)r * DD + c * 8);
        }
#pragma unroll
        for (int j = 0; j < 2; j++) {
            int idx = t + j * 256;
            int r = idx >> 3, c = idx & 7;
            cp16((char*)Vs[s] + r * 128 + ((c ^ (r & 7)) << 4), vc + (size_t)r * DD + c * 8);
        }
    };

    loadQ(); loadKV(0, 0); cp_commit();
    loadKV(1, 1); cp_commit();

    float m0 = -1e30f, m1 = -1e30f, l0 = 0.f, l1 = 0.f;
    float o[8][4];
#pragma unroll
    for (int i = 0; i < 8; i++)
#pragma unroll
        for (int k = 0; k < 4; k++) o[i][k] = 0.f;

    asm volatile("cp.async.wait_group 1;\n");
    __syncthreads();
    uint32_t aq[4][4];
    {
        const int qrow = w * 16 + (lane & 15);
#pragma unroll
        for (int ks = 0; ks < 4; ks++) {
            int kch = ks * 2 + (lane >> 4);
            ldsm4(aq[ks][0], aq[ks][1], aq[ks][2], aq[ks][3],
                  sQ + qrow * 128 + ((kch ^ (qrow & 7)) << 4));
        }
    }

    const int r0g = w * 16 + (lane >> 2);
    const int cb2 = (lane & 3) * 2;

    for (int ch = 0; ch < 8; ch++) {
        if (ch > 0) {
            if (ch < 7) { asm volatile("cp.async.wait_group 1;\n"); }
            else        { asm volatile("cp.async.wait_group 0;\n"); }
            __syncthreads();
        }
        const int s = ch & 1;

        float sc[8][4];
        {
            const __half* bp0 = Bg + (size_t)r0g * SS + ch * 64 + cb2;
            const __half* bp1 = bp0 + 8 * SS;
#pragma unroll
            for (int nj = 0; nj < 8; nj++) {
                float2 bv0 = __half22float2(*reinterpret_cast<const __half2*>(bp0 + nj * 8));
                float2 bv1 = __half22float2(*reinterpret_cast<const __half2*>(bp1 + nj * 8));
                sc[nj][0] = bv0.x; sc[nj][1] = bv0.y;
                sc[nj][2] = bv1.x; sc[nj][3] = bv1.y;
            }
        }

#pragma unroll
        for (int ks = 0; ks < 4; ks++) {
#pragma unroll
            for (int ng = 0; ng < 4; ng++) {
                int nrow = ng * 16 + (lane & 15);
                int kch = ks * 2 + (lane >> 4);
                uint32_t r0, r1, r2, r3;
                ldsm4(r0, r1, r2, r3, sK[s] + nrow * 128 + ((kch ^ (nrow & 7)) << 4));
                mma16816(sc[ng*2][0], sc[ng*2][1], sc[ng*2][2], sc[ng*2][3],
                         aq[ks][0], aq[ks][1], aq[ks][2], aq[ks][3], r0, r2);
                mma16816(sc[ng*2+1][0], sc[ng*2+1][1], sc[ng*2+1][2], sc[ng*2+1][3],
                         aq[ks][0], aq[ks][1], aq[ks][2], aq[ks][3], r1, r3);
            }
        }

        float rm0 = -1e30f, rm1 = -1e30f;
#pragma unroll
        for (int nj = 0; nj < 8; nj++) {
            rm0 = fmaxf(rm0, fmaxf(sc[nj][0], sc[nj][1]));
            rm1 = fmaxf(rm1, fmaxf(sc[nj][2], sc[nj][3]));
        }
        rm0 = fmaxf(rm0, __shfl_xor_sync(0xffffffffu, rm0, 1));
        rm0 = fmaxf(rm0, __shfl_xor_sync(0xffffffffu, rm0, 2));
        rm1 = fmaxf(rm1, __shfl_xor_sync(0xffffffffu, rm1, 1));
        rm1 = fmaxf(rm1, __shfl_xor_sync(0xffffffffu, rm1, 2));

        float nm0 = fmaxf(m0, rm0), nm1 = fmaxf(m1, rm1);
        float al0 = __expf(m0 - nm0), al1 = __expf(m1 - nm1);
        m0 = nm0; m1 = nm1;

        uint32_t h0[8], h1[8];
        float rs0 = 0.f, rs1 = 0.f;
#pragma unroll
        for (int nj = 0; nj < 8; nj++) {
            float e0 = __expf(sc[nj][0] - nm0);
            float e1 = __expf(sc[nj][1] - nm0);
            float e2 = __expf(sc[nj][2] - nm1);
            float e3 = __expf(sc[nj][3] - nm1);
            rs0 += e0 + e1; rs1 += e2 + e3;
            h0[nj] = h2_as_u32(__floats2half2_rn(e0, e1));
            h1[nj] = h2_as_u32(__floats2half2_rn(e2, e3));
        }
        rs0 += __shfl_xor_sync(0xffffffffu, rs0, 1);
        rs0 += __shfl_xor_sync(0xffffffffu, rs0, 2);
        rs1 += __shfl_xor_sync(0xffffffffu, rs1, 1);
        rs1 += __shfl_xor_sync(0xffffffffu, rs1, 2);
        l0 = l0 * al0 + rs0;
        l1 = l1 * al1 + rs1;
#pragma unroll
        for (int i = 0; i < 8; i++) {
            o[i][0] *= al0; o[i][1] *= al0;
            o[i][2] *= al1; o[i][3] *= al1;
        }

#pragma unroll
        for (int j = 0; j < 4; j++) {
#pragma unroll
            for (int pr = 0; pr < 4; pr++) {
                int kk = j * 16 + (lane & 15);
                int nch = pr * 2 + (lane >> 4);
                uint32_t r0, r1, r2, r3;
                ldsm4t(r0, r1, r2, r3, sV[s] + kk * 128 + ((nch ^ (kk & 7)) << 4));
                mma16816(o[pr*2][0], o[pr*2][1], o[pr*2][2], o[pr*2][3],
                         h0[2*j], h1[2*j], h0[2*j+1], h1[2*j+1], r0, r1);
                mma16816(o[pr*2+1][0], o[pr*2+1][1], o[pr*2+1][2], o[pr*2+1][3],
                         h0[2*j], h1[2*j], h0[2*j+1], h1[2*j+1], r2, r3);
            }
        }
        __syncthreads();
        if (ch + 2 < 8) { loadKV(s, ch + 2); cp_commit(); }
        else if (ch < 7) { cp_commit(); }
    }

    const float inv0 = 1.f / l0, inv1 = 1.f / l1;
    const int row0 = q0 + r0g;
    const int col0 = hh * DD + cb2;
    __half* o0 = outH + ((size_t)(b * SS) + row0) * HH + col0;
    __half* o1 = o0 + 8 * HH;
#pragma unroll
    for (int pj = 0; pj < 8; pj++) {
        *reinterpret_cast<__half2*>(o0 + pj * 8) = __floats2half2_rn(o[pj][0] * inv0, o[pj][1] * inv0);
        *reinterpret_cast<__half2*>(o1 + pj * 8) = __floats2half2_rn(o[pj][2] * inv1, o[pj][3] * inv1);
    }
}

// ---------------- mma.sync GEMM: 128x256 tile, warp 64x64, BK=32, 3 stages ----------------
// A stage: 128 rows x 64B (swizzle c^((r>>1)&3)); B stage: 32 rows x 512B (c^(k&7), 32 chunks).
// No smem staging: epilogue direct from registers. EPI: 6 QKV scatter, 3 residual, 4 GELU.
#define MG_STAGES 3
#define MG_ASTG   8192
#define MG_BSTG   16384
#define MG_DSM    73728

template<int EPI>
__global__ __launch_bounds__(256, 1) void mgemm_kernel(
    const __half* __restrict__ Ag, const __half* __restrict__ Bg,
    const float* __restrict__ bias,
    float* __restrict__ outF, __half* __restrict__ outH,
    int K, int N, float oscale)
{
    extern __shared__ __align__(16) char dyn[];
    const unsigned sb = smem_u32(dyn);

    const int t = threadIdx.x, w = t >> 5, lane = t & 31;
    const int wm = w >> 2, wn = w & 3;          // 2 x 4 warps, warp tile 64(M) x 64(N)
    const __half* A = Ag + (size_t)blockIdx.y * 128 * K;
    const int n0 = blockIdx.x * 256;

    float d[4][8][4];
#pragma unroll
    for (int i = 0; i < 4; i++)
#pragma unroll
        for (int j = 0; j < 8; j++)
#pragma unroll
            for (int k = 0; k < 4; k++) d[i][j][k] = 0.f;

    auto load_tiles = [&](int s, int k0) {
        char* as = dyn + s * MG_ASTG;
        char* bs = dyn + MG_STAGES * MG_ASTG + s * MG_BSTG;
#pragma unroll
        for (int i = 0; i < 2; i++) {           // A: 128 x 32 halves = 512 chunks
            int idx = t + i * 256;
            int r = idx >> 2, c = idx & 3;
            cp16(as + r * 64 + ((c ^ ((r >> 1) & 3)) << 4), A + (size_t)r * K + k0 + c * 8);
        }
#pragma unroll
        for (int i = 0; i < 4; i++) {           // B: 32 x 256 halves = 1024 chunks
            int idx = t + i * 256;
            int k = idx >> 5, c = idx & 31;
            cp16(bs + k * 512 + ((c ^ (k & 7)) << 4), Bg + (size_t)(k0 + k) * N + n0 + c * 8);
        }
    };

    const int nk = K >> 5;
    load_tiles(0, 0); cp_commit();
    load_tiles(1, 32); cp_commit();

    int s = 0;
    for (int kt = 0; kt < nk; kt++) {
        asm volatile("cp.async.wait_group 1;\n");
        __syncthreads();
        {
            int kn = kt + 2;
            if (kn < nk) {
                int sn = s + 2; if (sn >= MG_STAGES) sn -= MG_STAGES;
                load_tiles(sn, kn * 32);
            }
            cp_commit();
        }
        const unsigned abase = sb + s * MG_ASTG;
        const unsigned bbase = sb + MG_STAGES * MG_ASTG + s * MG_BSTG;

#pragma unroll
        for (int ks = 0; ks < 2; ks++) {
            uint32_t a[4][4], b[4][4];
#pragma unroll
            for (int mi = 0; mi < 4; mi++) {
                int row = wm * 64 + mi * 16 + (lane & 15);
                int kch = ks * 2 + (lane >> 4);
                ldsm4(a[mi][0], a[mi][1], a[mi][2], a[mi][3],
                      abase + row * 64 + ((kch ^ ((row >> 1) & 3)) << 4));
            }
#pragma unroll
            for (int pr = 0; pr < 4; pr++) {
                int kk = ks * 16 + (lane & 15);
                int nch = wn * 8 + pr * 2 + (lane >> 4);
                ldsm4t(b[pr][0], b[pr][1], b[pr][2], b[pr][3],
                       bbase + kk * 512 + ((nch ^ (kk & 7)) << 4));
            }
#pragma unroll
            for (int mi = 0; mi < 4; mi++)
#pragma unroll
                for (int nj = 0; nj < 8; nj++)
                    mma16816(d[mi][nj][0], d[mi][nj][1], d[mi][nj][2], d[mi][nj][3],
                             a[mi][0], a[mi][1], a[mi][2], a[mi][3],
                             b[nj >> 1][(nj & 1) * 2], b[nj >> 1][(nj & 1) * 2 + 1]);
        }
        if (++s == MG_STAGES) s = 0;
    }

    // ---- epilogue direct from registers ----
    const int gi0 = blockIdx.y * 128 + wm * 64 + (lane >> 2);
    const int gj0 = n0 + wn * 64 + (lane & 3) * 2;

#pragma unroll
    for (int nj = 0; nj < 8; nj++) {
        const int gj = gj0 + nj * 8;
        const float b0 = bias[gj], b1 = bias[gj + 1];

        if (EPI == 6) {
            const int which = gj / HH;
            const int col = gj - which * HH;
            const float f = (which == 0) ? oscale : 1.f;
            const int hhh = col >> 6, dd = col & 63;
            __half* base = outH + (size_t)which * QKV_STRIDE;
#pragma unroll
            for (int mi = 0; mi < 4; mi++) {
#pragma unroll
                for (int half = 0; half < 2; half++) {
                    int gi = gi0 + mi * 16 + half * 8;
                    int bb = gi >> 9, ss2 = gi & 511;
                    float v0 = (d[mi][nj][half * 2]     + b0) * f;
                    float v1 = (d[mi][nj][half * 2 + 1] + b1) * f;
                    *reinterpret_cast<__half2*>(
                        &base[(((size_t)(bb * NH_ + hhh) * SS + ss2) << 6) + dd]) =
                        __floats2half2_rn(v0, v1);
                }
            }
        } else if (EPI == 3) {
#pragma unroll
            for (int mi = 0; mi < 4; mi++) {
#pragma unroll
                for (int half = 0; half < 2; half++) {
                    int gi = gi0 + mi * 16 + half * 8;
                    float* dst = &outF[(size_t)gi * N + gj];
                    float2 old = *reinterpret_cast<float2*>(dst);
                    old.x += d[mi][nj][half * 2]     + b0;
                    old.y += d[mi][nj][half * 2 + 1] + b1;
                    *reinterpret_cast<float2*>(dst) = old;
                }
            }
        } else { // EPI == 4
#pragma unroll
            for (int mi = 0; mi < 4; mi++) {
#pragma unroll
                for (int half = 0; half < 2; half++) {
                    int gi = gi0 + mi * 16 + half * 8;
                    float x0 = d[mi][nj][half * 2]     + b0;
                    float x1 = d[mi][nj][half * 2 + 1] + b1;
                    float g0 = 0.5f * x0 * (1.f + erff(x0 * 0.70710678118654752f));
                    float g1 = 0.5f * x1 * (1.f + erff(x1 * 0.70710678118654752f));
                    *reinterpret_cast<__half2*>(&outH[(size_t)gi * N + gj]) =
                        __floats2half2_rn(g0, g1);
                }
            }
        }
    }
}

// ---------------- host ----------------
extern "C" void kernel_launch(void* const* d_in, const int* in_sizes, int n_in,
                              void* d_out, int out_size)
{
    const float* x         = (const float*)d_in[0];
    const float* attn_bias = (const float*)d_in[1];
    const float* ln1_g = (const float*)d_in[2];
    const float* ln1_b = (const float*)d_in[3];
    const float* wq = (const float*)d_in[4];
    const float* bq = (const float*)d_in[5];
    const float* wk = (const float*)d_in[6];
    const float* bk = (const float*)d_in[7];
    const float* wv = (const float*)d_in[8];
    const float* bv = (const float*)d_in[9];
    const float* wo = (const float*)d_in[10];
    const float* bo = (const float*)d_in[11];
    const float* ln2_g = (const float*)d_in[12];
    const float* ln2_b = (const float*)d_in[13];
    const float* w1 = (const float*)d_in[14];
    const float* b1 = (const float*)d_in[15];
    const float* w2 = (const float*)d_in[16];
    const float* b2 = (const float*)d_in[17];
    const float* fln_g = (const float*)d_in[18];
    const float* fln_b = (const float*)d_in[19];
    float* out = (float*)d_out;

    void* pv_ = nullptr;
    cudaGetSymbolAddress(&pv_, g_h);      float*  p_h    = (float*)pv_;
    cudaGetSymbolAddress(&pv_, g_y);      __half* p_y    = (__half*)pv_;
    cudaGetSymbolAddress(&pv_, g_qkv);    __half* p_qkv  = (__half*)pv_;
    cudaGetSymbolAddress(&pv_, g_attn);   __half* p_attn = (__half*)pv_;
    cudaGetSymbolAddress(&pv_, g_ff);     __half* p_ff   = (__half*)pv_;
    cudaGetSymbolAddress(&pv_, g_bias16); __half* p_b16  = (__half*)pv_;
    cudaGetSymbolAddress(&pv_, g_w16);    __half* p_w16  = (__half*)pv_;
    cudaGetSymbolAddress(&pv_, g_bqkv);   float*  p_bqkv = (float*)pv_;

    __half* wqkv16 = p_w16 + OFF_QKV;
    __half* wo16   = p_w16 + OFF_WO;
    __half* w116   = p_w16 + OFF_W1;
    __half* w216   = p_w16 + OFF_W2;

    cudaFuncSetAttribute(mgemm_kernel<6>, cudaFuncAttributeMaxDynamicSharedMemorySize, MG_DSM);
    cudaFuncSetAttribute(mgemm_kernel<3>, cudaFuncAttributeMaxDynamicSharedMemorySize, MG_DSM);
    cudaFuncSetAttribute(mgemm_kernel<4>, cudaFuncAttributeMaxDynamicSharedMemorySize, MG_DSM);

    // init launches
    initw_kernel<<<(unsigned)((NPAIRS + 255) / 256), 256>>>(wq, wk, wv, wo, w1, w2, p_w16);
    inith_kernel<<<(unsigned)((NCOPY4 + 255) / 256), 256>>>(x, p_h);
    initb_kernel<<<(LL * NQKV + 255) / 256, 256>>>(bq, bk, bv, p_bqkv);
    initab_kernel<<<(unsigned)((NBIAS / 2 + 255) / 256), 256>>>(attn_bias, p_b16);

    const dim3 blk(256);
    const dim3 grid_qkv(NQKV / 256, MR / 128);          // 9 x 64
    const dim3 grid_proj(HH / 256, MR / 128);           // 3 x 64
    const dim3 grid_ff1(FF_ / 256, MR / 128);           // 12 x 64
    const dim3 grid_fa(SS / 128, BB * NH_);
    const unsigned ln_blocks = MR / 8;

    for (int l = 0; l < LL; l++) {
        ln_kernel<<<ln_blocks, blk>>>(p_h, ln1_g + l * HH, ln1_b + l * HH, p_y, nullptr);
        mgemm_kernel<6><<<grid_qkv, blk, MG_DSM>>>(p_y, wqkv16 + (size_t)l * HH * NQKV,
                                                   p_bqkv + (size_t)l * NQKV,
                                                   nullptr, p_qkv, HH, NQKV, SCALE_Q);
        flash_kernel<<<grid_fa, blk>>>(p_qkv, p_qkv + QKV_STRIDE, p_qkv + 2 * QKV_STRIDE,
                                       p_b16, p_attn);
        mgemm_kernel<3><<<grid_proj, blk, MG_DSM>>>(p_attn, wo16 + (size_t)l * HHxHH, bo + l * HH,
                                                    p_h, nullptr, HH, HH, 1.f);
        ln_kernel<<<ln_blocks, blk>>>(p_h, ln2_g + l * HH, ln2_b + l * HH, p_y, nullptr);
        mgemm_kernel<4><<<grid_ff1, blk, MG_DSM>>>(p_y, w116 + (size_t)l * HHxFF, b1 + l * FF_,
                                                   nullptr, p_ff, HH, FF_, 1.f);
        mgemm_kernel<3><<<grid_proj, blk, MG_DSM>>>(p_ff, w216 + (size_t)l * HHxFF, b2 + l * HH,
                                                    p_h, nullptr, FF_, HH, 1.f);
    }
    ln_kernel<<<ln_blocks, blk>>>(p_h, fln_g, fln_b, nullptr, out);
}

// round 15
// speedup vs baseline: 1.1497x; 1.1497x over previous
#include <cuda_runtime.h>
#include <cuda_fp16.h>
#include <cstdint>

// ---------------- problem constants ----------------
#define BB   16
#define SS   512
#define HH   768
#define NH_  12
#define DD   64
#define FF_  3072
#define LL   4
#define MR   (BB*SS)
#define SCALE_Q 0.125f
#define LN_EPS 1e-5f

#define HHxHH   (HH*HH)
#define HHxFF   (HH*FF_)
#define NQKV    (3*HH)                 // 2304
#define QKV_STRIDE ((size_t)MR*HH)
#define NBIAS   ((size_t)BB*NH_*SS*SS)

// ---------------- scratch ----------------
__device__ __align__(16) float  g_h[(size_t)MR*HH];
__device__ __align__(16) __half g_y[(size_t)MR*HH];
__device__ __align__(16) __half g_qkv[(size_t)3*MR*HH];      // q|k|v each [B,NH,S,D]
__device__ __align__(16) __half g_attn[(size_t)MR*HH];       // [B,S,H]
__device__ __align__(16) __half g_ff[(size_t)MR*FF_];
__device__ __align__(16) __half g_bias16[NBIAS];             // fp16 attn_bias
__device__ __align__(16) __half g_w16[(size_t)LL*(4*HHxHH + 2*HHxFF)];
__device__ __align__(16) float  g_bqkv[(size_t)LL*NQKV];

#define OFF_QKV ((size_t)0)
#define OFF_WO  ((size_t)3*LL*HHxHH)
#define OFF_W1  ((size_t)4*LL*HHxHH)
#define OFF_W2  ((size_t)4*LL*HHxHH + (size_t)LL*HHxFF)

// ---------------- init kernels ----------------
#define NPAIRS ((size_t)LL*(4*HHxHH + 2*HHxFF)/2)
#define NCOPY4 ((size_t)MR*HH/4)

__global__ void initw_kernel(
    const float* __restrict__ wq, const float* __restrict__ wk,
    const float* __restrict__ wv, const float* __restrict__ wo,
    const float* __restrict__ w1, const float* __restrict__ w2,
    __half* __restrict__ dst)
{
    const size_t NP = (size_t)LL * HHxHH / 2;
    const size_t NF = (size_t)LL * HHxFF / 2;
    size_t i = (size_t)blockIdx.x * blockDim.x + threadIdx.x;
    if (i >= NPAIRS) return;
    const float* src; size_t off, dpi;
    if (i < 3 * NP) {
        size_t g = i / NP; off = i - g * NP;
        src = (g == 0) ? wq : (g == 1) ? wk : wv;
        size_t l  = off / (HHxHH / 2);
        size_t r  = off - l * (HHxHH / 2);
        size_t k  = r / (HH / 2);
        size_t nc = r - k * (HH / 2);
        dpi = l * ((size_t)HH * NQKV / 2) + k * (NQKV / 2) + g * (HH / 2) + nc;
    } else {
        dpi = i;
        if (i < 4 * NP) { src = wo; off = i - 3 * NP; }
        else {
            size_t j = i - 4 * NP;
            size_t g = j / NF; off = j - g * NF;
            src = g ? w2 : w1;
        }
    }
    float2 f = reinterpret_cast<const float2*>(src)[off];
    reinterpret_cast<__half2*>(dst)[dpi] = __floats2half2_rn(f.x, f.y);
}

__global__ void inith_kernel(const float* __restrict__ x, float* __restrict__ h) {
    size_t i = (size_t)blockIdx.x * blockDim.x + threadIdx.x;
    if (i < NCOPY4)
        reinterpret_cast<float4*>(h)[i] = reinterpret_cast<const float4*>(x)[i];
}

__global__ void initb_kernel(const float* __restrict__ bq, const float* __restrict__ bk,
                             const float* __restrict__ bv, float* __restrict__ dst) {
    int i = blockIdx.x * blockDim.x + threadIdx.x;
    if (i >= LL * NQKV) return;
    int l = i / NQKV, n = i - l * NQKV;
    float v = (n < HH) ? bq[l * HH + n]
            : (n < 2 * HH) ? bk[l * HH + n - HH]
            : bv[l * HH + n - 2 * HH];
    dst[i] = v;
}

__global__ void initab_kernel(const float* __restrict__ src, __half* __restrict__ dst) {
    size_t i = (size_t)blockIdx.x * blockDim.x + threadIdx.x;
    if (i < NBIAS / 2) {
        float2 f = reinterpret_cast<const float2*>(src)[i];
        reinterpret_cast<__half2*>(dst)[i] = __floats2half2_rn(f.x, f.y);
    }
}

// ---------------- LayerNorm: warp-per-row, 8 rows/block ----------------
__global__ __launch_bounds__(256) void ln_kernel(
    const float* __restrict__ in, const float* __restrict__ g, const float* __restrict__ b,
    __half* __restrict__ outH, float* __restrict__ outF)
{
    const int w = threadIdx.x >> 5, lane = threadIdx.x & 31;
    const int row = blockIdx.x * 8 + w;
    const float* x = in + (size_t)row * HH;

    float4 v[6];
    float s = 0.f, s2 = 0.f;
#pragma unroll
    for (int i = 0; i < 6; i++) {
        v[i] = *reinterpret_cast<const float4*>(x + lane * 4 + i * 128);
        s  += v[i].x + v[i].y + v[i].z + v[i].w;
        s2 += v[i].x * v[i].x + v[i].y * v[i].y + v[i].z * v[i].z + v[i].w * v[i].w;
    }
#pragma unroll
    for (int o = 16; o; o >>= 1) {
        s  += __shfl_xor_sync(0xffffffffu, s,  o);
        s2 += __shfl_xor_sync(0xffffffffu, s2, o);
    }
    const float mean = s * (1.f / HH);
    const float rstd = rsqrtf(s2 * (1.f / HH) - mean * mean + LN_EPS);

#pragma unroll
    for (int i = 0; i < 6; i++) {
        const int c = lane * 4 + i * 128;
        float o0 = (v[i].x - mean) * rstd * g[c]     + b[c];
        float o1 = (v[i].y - mean) * rstd * g[c + 1] + b[c + 1];
        float o2 = (v[i].z - mean) * rstd * g[c + 2] + b[c + 2];
        float o3 = (v[i].w - mean) * rstd * g[c + 3] + b[c + 3];
        if (outH) {
            __half2 p0 = __floats2half2_rn(o0, o1);
            __half2 p1 = __floats2half2_rn(o2, o3);
            uint2 pk = { *reinterpret_cast<uint32_t*>(&p0), *reinterpret_cast<uint32_t*>(&p1) };
            *reinterpret_cast<uint2*>(outH + (size_t)row * HH + c) = pk;
        } else {
            float4 ov = { o0, o1, o2, o3 };
            *reinterpret_cast<float4*>(outF + (size_t)row * HH + c) = ov;
        }
    }
}

// ---------------- asm helpers ----------------
__device__ __forceinline__ void cp16(void* smem, const void* gmem) {
    unsigned sa = (unsigned)__cvta_generic_to_shared(smem);
    asm volatile("cp.async.cg.shared.global [%0], [%1], 16;\n" :: "r"(sa), "l"(gmem));
}
__device__ __forceinline__ void cp_commit() { asm volatile("cp.async.commit_group;\n"); }
__device__ __forceinline__ unsigned smem_u32(const void* p) {
    return (unsigned)__cvta_generic_to_shared(p);
}
__device__ __forceinline__ uint32_t h2_as_u32(__half2 h) {
    return *reinterpret_cast<uint32_t*>(&h);
}
__device__ __forceinline__ void ldsm4(uint32_t& r0, uint32_t& r1, uint32_t& r2, uint32_t& r3,
                                      unsigned addr) {
    asm volatile("ldmatrix.sync.aligned.m8n8.x4.shared.b16 {%0,%1,%2,%3}, [%4];"
                 : "=r"(r0), "=r"(r1), "=r"(r2), "=r"(r3) : "r"(addr));
}
__device__ __forceinline__ void ldsm4t(uint32_t& r0, uint32_t& r1, uint32_t& r2, uint32_t& r3,
                                       unsigned addr) {
    asm volatile("ldmatrix.sync.aligned.m8n8.x4.trans.shared.b16 {%0,%1,%2,%3}, [%4];"
                 : "=r"(r0), "=r"(r1), "=r"(r2), "=r"(r3) : "r"(addr));
}
__device__ __forceinline__ void mma16816(float& d0, float& d1, float& d2, float& d3,
                                         uint32_t a0, uint32_t a1, uint32_t a2, uint32_t a3,
                                         uint32_t b0, uint32_t b1) {
    asm volatile(
        "mma.sync.aligned.m16n8k16.row.col.f32.f16.f16.f32 "
        "{%0,%1,%2,%3}, {%4,%5,%6,%7}, {%8,%9}, {%0,%1,%2,%3};"
        : "+f"(d0), "+f"(d1), "+f"(d2), "+f"(d3)
        : "r"(a0), "r"(a1), "r"(a2), "r"(a3), "r"(b0), "r"(b1));
}

// ---------------- flash attention (unchanged; best-known) ----------------
__global__ __launch_bounds__(256, 2) void flash_kernel(
    const __half* __restrict__ qg, const __half* __restrict__ kg,
    const __half* __restrict__ vg, const __half* __restrict__ biasg,
    __half* __restrict__ outH)
{
    __shared__ __align__(16) __half Qs[128 * 64];
    __shared__ __align__(16) __half Ks[2][64 * 64];
    __shared__ __align__(16) __half Vs[2][64 * 64];

    const int t = threadIdx.x, w = t >> 5, lane = t & 31;
    const int z = blockIdx.y;
    const int b = z / NH_, hh = z - b * NH_;
    const int q0 = blockIdx.x * 128;

    const __half* Qg = qg + (size_t)z * SS * DD + (size_t)q0 * DD;
    const __half* Kg = kg + (size_t)z * SS * DD;
    const __half* Vg = vg + (size_t)z * SS * DD;
    const __half* Bg = biasg + (size_t)z * SS * SS + (size_t)q0 * SS;

    const unsigned sQ = smem_u32(Qs);
    const unsigned sK[2] = { smem_u32(Ks[0]), smem_u32(Ks[1]) };
    const unsigned sV[2] = { smem_u32(Vs[0]), smem_u32(Vs[1]) };

    auto loadQ = [&]() {
#pragma unroll
        for (int j = 0; j < 4; j++) {
            int idx = t + j * 256;
            int r = idx >> 3, c = idx & 7;
            cp16((char*)Qs + r * 128 + ((c ^ (r & 7)) << 4), Qg + (size_t)r * DD + c * 8);
        }
    };
    auto loadKV = [&](int s, int chunk) {
        const __half* kc = Kg + (size_t)chunk * 64 * DD;
        const __half* vc = Vg + (size_t)chunk * 64 * DD;
#pragma unroll
        for (int j = 0; j < 2; j++) {
            int idx = t + j * 256;
            int r = idx >> 3, c = idx & 7;
            cp16((char*)Ks[s] + r * 128 + ((c ^ (r & 7)) << 4), kc + (size_t)r * DD + c * 8);
        }
#pragma unroll
        for (int j = 0; j < 2; j++) {
            int idx = t + j * 256;
            int r = idx >> 3, c = idx & 7;
            cp16((char*)Vs[s] + r * 128 + ((c ^ (r & 7)) << 4), vc + (size_t)r * DD + c * 8);
        }
    };

    loadQ(); loadKV(0, 0); cp_commit();
    loadKV(1, 1); cp_commit();

    float m0 = -1e30f, m1 = -1e30f, l0 = 0.f, l1 = 0.f;
    float o[8][4];
#pragma unroll
    for (int i = 0; i < 8; i++)
#pragma unroll
        for (int k = 0; k < 4; k++) o[i][k] = 0.f;

    asm volatile("cp.async.wait_group 1;\n");
    __syncthreads();
    uint32_t aq[4][4];
    {
        const int qrow = w * 16 + (lane & 15);
#pragma unroll
        for (int ks = 0; ks < 4; ks++) {
            int kch = ks * 2 + (lane >> 4);
            ldsm4(aq[ks][0], aq[ks][1], aq[ks][2], aq[ks][3],
                  sQ + qrow * 128 + ((kch ^ (qrow & 7)) << 4));
        }
    }

    const int r0g = w * 16 + (lane >> 2);
    const int cb2 = (lane & 3) * 2;

    for (int ch = 0; ch < 8; ch++) {
        if (ch > 0) {
            if (ch < 7) { asm volatile("cp.async.wait_group 1;\n"); }
            else        { asm volatile("cp.async.wait_group 0;\n"); }
            __syncthreads();
        }
        const int s = ch & 1;

        float sc[8][4];
        {
            const __half* bp0 = Bg + (size_t)r0g * SS + ch * 64 + cb2;
            const __half* bp1 = bp0 + 8 * SS;
#pragma unroll
            for (int nj = 0; nj < 8; nj++) {
                float2 bv0 = __half22float2(*reinterpret_cast<const __half2*>(bp0 + nj * 8));
                float2 bv1 = __half22float2(*reinterpret_cast<const __half2*>(bp1 + nj * 8));
                sc[nj][0] = bv0.x; sc[nj][1] = bv0.y;
                sc[nj][2] = bv1.x; sc[nj][3] = bv1.y;
            }
        }

#pragma unroll
        for (int ks = 0; ks < 4; ks++) {
#pragma unroll
            for (int ng = 0; ng < 4; ng++) {
                int nrow = ng * 16 + (lane & 15);
                int kch = ks * 2 + (lane >> 4);
                uint32_t r0, r1, r2, r3;
                ldsm4(r0, r1, r2, r3, sK[s] + nrow * 128 + ((kch ^ (nrow & 7)) << 4));
                mma16816(sc[ng*2][0], sc[ng*2][1], sc[ng*2][2], sc[ng*2][3],
                         aq[ks][0], aq[ks][1], aq[ks][2], aq[ks][3], r0, r2);
                mma16816(sc[ng*2+1][0], sc[ng*2+1][1], sc[ng*2+1][2], sc[ng*2+1][3],
                         aq[ks][0], aq[ks][1], aq[ks][2], aq[ks][3], r1, r3);
            }
        }

        float rm0 = -1e30f, rm1 = -1e30f;
#pragma unroll
        for (int nj = 0; nj < 8; nj++) {
            rm0 = fmaxf(rm0, fmaxf(sc[nj][0], sc[nj][1]));
            rm1 = fmaxf(rm1, fmaxf(sc[nj][2], sc[nj][3]));
        }
        rm0 = fmaxf(rm0, __shfl_xor_sync(0xffffffffu, rm0, 1));
        rm0 = fmaxf(rm0, __shfl_xor_sync(0xffffffffu, rm0, 2));
        rm1 = fmaxf(rm1, __shfl_xor_sync(0xffffffffu, rm1, 1));
        rm1 = fmaxf(rm1, __shfl_xor_sync(0xffffffffu, rm1, 2));

        float nm0 = fmaxf(m0, rm0), nm1 = fmaxf(m1, rm1);
        float al0 = __expf(m0 - nm0), al1 = __expf(m1 - nm1);
        m0 = nm0; m1 = nm1;

        uint32_t h0[8], h1[8];
        float rs0 = 0.f, rs1 = 0.f;
#pragma unroll
        for (int nj = 0; nj < 8; nj++) {
            float e0 = __expf(sc[nj][0] - nm0);
            float e1 = __expf(sc[nj][1] - nm0);
            float e2 = __expf(sc[nj][2] - nm1);
            float e3 = __expf(sc[nj][3] - nm1);
            rs0 += e0 + e1; rs1 += e2 + e3;
            h0[nj] = h2_as_u32(__floats2half2_rn(e0, e1));
            h1[nj] = h2_as_u32(__floats2half2_rn(e2, e3));
        }
        rs0 += __shfl_xor_sync(0xffffffffu, rs0, 1);
        rs0 += __shfl_xor_sync(0xffffffffu, rs0, 2);
        rs1 += __shfl_xor_sync(0xffffffffu, rs1, 1);
        rs1 += __shfl_xor_sync(0xffffffffu, rs1, 2);
        l0 = l0 * al0 + rs0;
        l1 = l1 * al1 + rs1;
#pragma unroll
        for (int i = 0; i < 8; i++) {
            o[i][0] *= al0; o[i][1] *= al0;
            o[i][2] *= al1; o[i][3] *= al1;
        }

#pragma unroll
        for (int j = 0; j < 4; j++) {
#pragma unroll
            for (int pr = 0; pr < 4; pr++) {
                int kk = j * 16 + (lane & 15);
                int nch = pr * 2 + (lane >> 4);
                uint32_t r0, r1, r2, r3;
                ldsm4t(r0, r1, r2, r3, sV[s] + kk * 128 + ((nch ^ (kk & 7)) << 4));
                mma16816(o[pr*2][0], o[pr*2][1], o[pr*2][2], o[pr*2][3],
                         h0[2*j], h1[2*j], h0[2*j+1], h1[2*j+1], r0, r1);
                mma16816(o[pr*2+1][0], o[pr*2+1][1], o[pr*2+1][2], o[pr*2+1][3],
                         h0[2*j], h1[2*j], h0[2*j+1], h1[2*j+1], r2, r3);
            }
        }
        __syncthreads();
        if (ch + 2 < 8) { loadKV(s, ch + 2); cp_commit(); }
        else if (ch < 7) { cp_commit(); }
    }

    const float inv0 = 1.f / l0, inv1 = 1.f / l1;
    const int row0 = q0 + r0g;
    const int col0 = hh * DD + cb2;
    __half* o0 = outH + ((size_t)(b * SS) + row0) * HH + col0;
    __half* o1 = o0 + 8 * HH;
#pragma unroll
    for (int pj = 0; pj < 8; pj++) {
        *reinterpret_cast<__half2*>(o0 + pj * 8) = __floats2half2_rn(o[pj][0] * inv0, o[pj][1] * inv0);
        *reinterpret_cast<__half2*>(o1 + pj * 8) = __floats2half2_rn(o[pj][2] * inv1, o[pj][3] * inv1);
    }
}

// ---------------- mma.sync GEMM: 128x128 CTA tile, 4 warps (2x2) of 64x64, BK=32, 3 stages ----
// A stage: 128 rows x 64B (swizzle c^((r>>1)&3)); B stage: 32 rows x 256B (c^(k&7)).
// 128 threads/CTA -> 2 CTAs/SM. Epilogue direct from registers.
// EPI: 6 QKV scatter, 3 residual +=, 4 GELU.
#define MG_STAGES 3
#define MG_ASTG   8192
#define MG_BSTG   8192
#define MG_DSM    49152

template<int EPI>
__global__ __launch_bounds__(128) void mgemm_kernel(
    const __half* __restrict__ Ag, const __half* __restrict__ Bg,
    const float* __restrict__ bias,
    float* __restrict__ outF, __half* __restrict__ outH,
    int K, int N, float oscale)
{
    extern __shared__ __align__(16) char dyn[];
    const unsigned sb = smem_u32(dyn);

    const int t = threadIdx.x, w = t >> 5, lane = t & 31;
    const int wm = w >> 1, wn = w & 1;          // 2 x 2 warps, warp tile 64(M) x 64(N)
    const __half* A = Ag + (size_t)blockIdx.y * 128 * K;
    const int n0 = blockIdx.x * 128;

    float d[4][8][4];
#pragma unroll
    for (int i = 0; i < 4; i++)
#pragma unroll
        for (int j = 0; j < 8; j++)
#pragma unroll
            for (int k = 0; k < 4; k++) d[i][j][k] = 0.f;

    auto load_tiles = [&](int s, int k0) {
        char* as = dyn + s * MG_ASTG;
        char* bs = dyn + MG_STAGES * MG_ASTG + s * MG_BSTG;
#pragma unroll
        for (int i = 0; i < 4; i++) {           // A: 128 x 32 halves = 512 chunks
            int idx = t + i * 128;
            int r = idx >> 2, c = idx & 3;
            cp16(as + r * 64 + ((c ^ ((r >> 1) & 3)) << 4), A + (size_t)r * K + k0 + c * 8);
        }
#pragma unroll
        for (int i = 0; i < 4; i++) {           // B: 32 x 128 halves = 512 chunks
            int idx = t + i * 128;
            int k = idx >> 4, c = idx & 15;
            cp16(bs + k * 256 + ((c ^ (k & 7)) << 4), Bg + (size_t)(k0 + k) * N + n0 + c * 8);
        }
    };

    const int nk = K >> 5;
    load_tiles(0, 0); cp_commit();
    load_tiles(1, 32); cp_commit();

    int s = 0;
    for (int kt = 0; kt < nk; kt++) {
        asm volatile("cp.async.wait_group 1;\n");
        __syncthreads();
        {
            int kn = kt + 2;
            if (kn < nk) {
                int sn = s + 2; if (sn >= MG_STAGES) sn -= MG_STAGES;
                load_tiles(sn, kn * 32);
            }
            cp_commit();
        }
        const unsigned abase = sb + s * MG_ASTG;
        const unsigned bbase = sb + MG_STAGES * MG_ASTG + s * MG_BSTG;

#pragma unroll
        for (int ks = 0; ks < 2; ks++) {
            uint32_t a[4][4], b[4][4];
#pragma unroll
            for (int mi = 0; mi < 4; mi++) {
                int row = wm * 64 + mi * 16 + (lane & 15);
                int kch = ks * 2 + (lane >> 4);
                ldsm4(a[mi][0], a[mi][1], a[mi][2], a[mi][3],
                      abase + row * 64 + ((kch ^ ((row >> 1) & 3)) << 4));
            }
#pragma unroll
            for (int pr = 0; pr < 4; pr++) {
                int kk = ks * 16 + (lane & 15);
                int nch = wn * 8 + pr * 2 + (lane >> 4);
                ldsm4t(b[pr][0], b[pr][1], b[pr][2], b[pr][3],
                       bbase + kk * 256 + ((nch ^ (kk & 7)) << 4));
            }
#pragma unroll
            for (int mi = 0; mi < 4; mi++)
#pragma unroll
                for (int nj = 0; nj < 8; nj++)
                    mma16816(d[mi][nj][0], d[mi][nj][1], d[mi][nj][2], d[mi][nj][3],
                             a[mi][0], a[mi][1], a[mi][2], a[mi][3],
                             b[nj >> 1][(nj & 1) * 2], b[nj >> 1][(nj & 1) * 2 + 1]);
        }
        if (++s == MG_STAGES) s = 0;
    }

    // ---- epilogue direct from registers ----
    const int gi0 = blockIdx.y * 128 + wm * 64 + (lane >> 2);
    const int gj0 = n0 + wn * 64 + (lane & 3) * 2;

#pragma unroll
    for (int nj = 0; nj < 8; nj++) {
        const int gj = gj0 + nj * 8;
        const float b0 = bias[gj], b1 = bias[gj + 1];

        if (EPI == 6) {
            const int which = gj / HH;          // tile (128) never spans 768 boundaries
            const int col = gj - which * HH;
            const float f = (which == 0) ? oscale : 1.f;
            const int hhh = col >> 6, dd = col & 63;
            __half* base = outH + (size_t)which * QKV_STRIDE;
#pragma unroll
            for (int mi = 0; mi < 4; mi++) {
#pragma unroll
                for (int half = 0; half < 2; half++) {
                    int gi = gi0 + mi * 16 + half * 8;
                    int bb = gi >> 9, ss2 = gi & 511;
                    float v0 = (d[mi][nj][half * 2]     + b0) * f;
                    float v1 = (d[mi][nj][half * 2 + 1] + b1) * f;
                    *reinterpret_cast<__half2*>(
                        &base[(((size_t)(bb * NH_ + hhh) * SS + ss2) << 6) + dd]) =
                        __floats2half2_rn(v0, v1);
                }
            }
        } else if (EPI == 3) {
#pragma unroll
            for (int mi = 0; mi < 4; mi++) {
#pragma unroll
                for (int half = 0; half < 2; half++) {
                    int gi = gi0 + mi * 16 + half * 8;
                    float* dst = &outF[(size_t)gi * N + gj];
                    float2 old = *reinterpret_cast<float2*>(dst);
                    old.x += d[mi][nj][half * 2]     + b0;
                    old.y += d[mi][nj][half * 2 + 1] + b1;
                    *reinterpret_cast<float2*>(dst) = old;
                }
            }
        } else { // EPI == 4
#pragma unroll
            for (int mi = 0; mi < 4; mi++) {
#pragma unroll
                for (int half = 0; half < 2; half++) {
                    int gi = gi0 + mi * 16 + half * 8;
                    float x0 = d[mi][nj][half * 2]     + b0;
                    float x1 = d[mi][nj][half * 2 + 1] + b1;
                    float g0 = 0.5f * x0 * (1.f + erff(x0 * 0.70710678118654752f));
                    float g1 = 0.5f * x1 * (1.f + erff(x1 * 0.70710678118654752f));
                    *reinterpret_cast<__half2*>(&outH[(size_t)gi * N + gj]) =
                        __floats2half2_rn(g0, g1);
                }
            }
        }
    }
}

// ---------------- host ----------------
extern "C" void kernel_launch(void* const* d_in, const int* in_sizes, int n_in,
                              void* d_out, int out_size)
{
    const float* x         = (const float*)d_in[0];
    const float* attn_bias = (const float*)d_in[1];
    const float* ln1_g = (const float*)d_in[2];
    const float* ln1_b = (const float*)d_in[3];
    const float* wq = (const float*)d_in[4];
    const float* bq = (const float*)d_in[5];
    const float* wk = (const float*)d_in[6];
    const float* bk = (const float*)d_in[7];
    const float* wv = (const float*)d_in[8];
    const float* bv = (const float*)d_in[9];
    const float* wo = (const float*)d_in[10];
    const float* bo = (const float*)d_in[11];
    const float* ln2_g = (const float*)d_in[12];
    const float* ln2_b = (const float*)d_in[13];
    const float* w1 = (const float*)d_in[14];
    const float* b1 = (const float*)d_in[15];
    const float* w2 = (const float*)d_in[16];
    const float* b2 = (const float*)d_in[17];
    const float* fln_g = (const float*)d_in[18];
    const float* fln_b = (const float*)d_in[19];
    float* out = (float*)d_out;

    void* pv_ = nullptr;
    cudaGetSymbolAddress(&pv_, g_h);      float*  p_h    = (float*)pv_;
    cudaGetSymbolAddress(&pv_, g_y);      __half* p_y    = (__half*)pv_;
    cudaGetSymbolAddress(&pv_, g_qkv);    __half* p_qkv  = (__half*)pv_;
    cudaGetSymbolAddress(&pv_, g_attn);   __half* p_attn = (__half*)pv_;
    cudaGetSymbolAddress(&pv_, g_ff);     __half* p_ff   = (__half*)pv_;
    cudaGetSymbolAddress(&pv_, g_bias16); __half* p_b16  = (__half*)pv_;
    cudaGetSymbolAddress(&pv_, g_w16);    __half* p_w16  = (__half*)pv_;
    cudaGetSymbolAddress(&pv_, g_bqkv);   float*  p_bqkv = (float*)pv_;

    __half* wqkv16 = p_w16 + OFF_QKV;
    __half* wo16   = p_w16 + OFF_WO;
    __half* w116   = p_w16 + OFF_W1;
    __half* w216   = p_w16 + OFF_W2;

    cudaFuncSetAttribute(mgemm_kernel<6>, cudaFuncAttributeMaxDynamicSharedMemorySize, MG_DSM);
    cudaFuncSetAttribute(mgemm_kernel<3>, cudaFuncAttributeMaxDynamicSharedMemorySize, MG_DSM);
    cudaFuncSetAttribute(mgemm_kernel<4>, cudaFuncAttributeMaxDynamicSharedMemorySize, MG_DSM);

    // init launches
    initw_kernel<<<(unsigned)((NPAIRS + 255) / 256), 256>>>(wq, wk, wv, wo, w1, w2, p_w16);
    inith_kernel<<<(unsigned)((NCOPY4 + 255) / 256), 256>>>(x, p_h);
    initb_kernel<<<(LL * NQKV + 255) / 256, 256>>>(bq, bk, bv, p_bqkv);
    initab_kernel<<<(unsigned)((NBIAS / 2 + 255) / 256), 256>>>(attn_bias, p_b16);

    const dim3 blk(256);
    const dim3 blk128(128);
    const dim3 grid_qkv(NQKV / 128, MR / 128);          // 18 x 64
    const dim3 grid_proj(HH / 128, MR / 128);           // 6 x 64
    const dim3 grid_ff1(FF_ / 128, MR / 128);           // 24 x 64
    const dim3 grid_fa(SS / 128, BB * NH_);
    const unsigned ln_blocks = MR / 8;

    for (int l = 0; l < LL; l++) {
        ln_kernel<<<ln_blocks, blk>>>(p_h, ln1_g + l * HH, ln1_b + l * HH, p_y, nullptr);
        mgemm_kernel<6><<<grid_qkv, blk128, MG_DSM>>>(p_y, wqkv16 + (size_t)l * HH * NQKV,
                                                      p_bqkv + (size_t)l * NQKV,
                                                      nullptr, p_qkv, HH, NQKV, SCALE_Q);
        flash_kernel<<<grid_fa, blk>>>(p_qkv, p_qkv + QKV_STRIDE, p_qkv + 2 * QKV_STRIDE,
                                       p_b16, p_attn);
        mgemm_kernel<3><<<grid_proj, blk128, MG_DSM>>>(p_attn, wo16 + (size_t)l * HHxHH, bo + l * HH,
                                                       p_h, nullptr, HH, HH, 1.f);
        ln_kernel<<<ln_blocks, blk>>>(p_h, ln2_g + l * HH, ln2_b + l * HH, p_y, nullptr);
        mgemm_kernel<4><<<grid_ff1, blk128, MG_DSM>>>(p_y, w116 + (size_t)l * HHxFF, b1 + l * FF_,
                                                      nullptr, p_ff, HH, FF_, 1.f);
        mgemm_kernel<3><<<grid_proj, blk128, MG_DSM>>>(p_ff, w216 + (size_t)l * HHxFF, b2 + l * HH,
                                                       p_h, nullptr, FF_, HH, 1.f);
    }
    ln_kernel<<<ln_blocks, blk>>>(p_h, fln_g, fln_b, nullptr, out);
}

// round 16
// speedup vs baseline: 1.2586x; 1.0947x over previous
#include <cuda_runtime.h>
#include <cuda_fp16.h>
#include <cstdint>

// ---------------- problem constants ----------------
#define BB   16
#define SS   512
#define HH   768
#define NH_  12
#define DD   64
#define FF_  3072
#define LL   4
#define MR   (BB*SS)
#define SCALE_Q 0.125f
#define LN_EPS 1e-5f

#define HHxHH   (HH*HH)
#define HHxFF   (HH*FF_)
#define NQKV    (3*HH)                 // 2304
#define QKV_STRIDE ((size_t)MR*HH)
#define NBIAS   ((size_t)BB*NH_*SS*SS)

// ---------------- scratch ----------------
__device__ __align__(16) float  g_h[(size_t)MR*HH];
__device__ __align__(16) __half g_y[(size_t)MR*HH];
__device__ __align__(16) __half g_qkv[(size_t)3*MR*HH];      // q|k|v each [B,NH,S,D]
__device__ __align__(16) __half g_attn[(size_t)MR*HH];       // [B,S,H]
__device__ __align__(16) __half g_ff[(size_t)MR*FF_];
__device__ __align__(16) __half g_bias16[NBIAS];             // fp16 attn_bias
__device__ __align__(16) __half g_w16[(size_t)LL*(4*HHxHH + 2*HHxFF)];
__device__ __align__(16) float  g_bqkv[(size_t)LL*NQKV];

#define OFF_QKV ((size_t)0)
#define OFF_WO  ((size_t)3*LL*HHxHH)
#define OFF_W1  ((size_t)4*LL*HHxHH)
#define OFF_W2  ((size_t)4*LL*HHxHH + (size_t)LL*HHxFF)

// ---------------- single fused init kernel ----------------
#define NPAIRS ((size_t)LL*(4*HHxHH + 2*HHxFF)/2)     // 14155776 weight half2 pairs
#define NCOPY4 ((size_t)MR*HH/4)                      // 1572864 h float4s
#define NBQKV  ((size_t)LL*NQKV)                      // 9216 qkv bias floats
#define NAB2   (NBIAS/2)                              // 25165824 attn-bias half2 pairs
#define T_W    NPAIRS
#define T_H    (T_W + NCOPY4)
#define T_B    (T_H + NBQKV)
#define T_AB   (T_B + NAB2)

__global__ void init_kernel(
    const float* __restrict__ x,
    const float* __restrict__ attn_bias,
    const float* __restrict__ wq, const float* __restrict__ wk,
    const float* __restrict__ wv, const float* __restrict__ wo,
    const float* __restrict__ w1, const float* __restrict__ w2,
    const float* __restrict__ bq, const float* __restrict__ bk,
    const float* __restrict__ bv,
    float* __restrict__ h, __half* __restrict__ wdst,
    float* __restrict__ bdst, __half* __restrict__ abdst)
{
    size_t i = (size_t)blockIdx.x * blockDim.x + threadIdx.x;
    if (i < T_W) {
        // weights fp32 -> fp16; wq/wk/wv interleaved into [l][k][2304]
        const size_t NP = (size_t)LL * HHxHH / 2;
        const size_t NF = (size_t)LL * HHxFF / 2;
        const float* src; size_t off, dpi;
        if (i < 3 * NP) {
            size_t g = i / NP; off = i - g * NP;
            src = (g == 0) ? wq : (g == 1) ? wk : wv;
            size_t l  = off / (HHxHH / 2);
            size_t r  = off - l * (HHxHH / 2);
            size_t k  = r / (HH / 2);
            size_t nc = r - k * (HH / 2);
            dpi = l * ((size_t)HH * NQKV / 2) + k * (NQKV / 2) + g * (HH / 2) + nc;
        } else {
            dpi = i;
            if (i < 4 * NP) { src = wo; off = i - 3 * NP; }
            else {
                size_t j = i - 4 * NP;
                size_t g = j / NF; off = j - g * NF;
                src = g ? w2 : w1;
            }
        }
        float2 f = reinterpret_cast<const float2*>(src)[off];
        reinterpret_cast<__half2*>(wdst)[dpi] = __floats2half2_rn(f.x, f.y);
    } else if (i < T_H) {
        size_t j = i - T_W;
        reinterpret_cast<float4*>(h)[j] = reinterpret_cast<const float4*>(x)[j];
    } else if (i < T_B) {
        size_t j = i - T_H;
        int l = (int)(j / NQKV), n = (int)(j - (size_t)l * NQKV);
        float v = (n < HH) ? bq[l * HH + n]
                : (n < 2 * HH) ? bk[l * HH + n - HH]
                : bv[l * HH + n - 2 * HH];
        bdst[j] = v;
    } else if (i < T_AB) {
        size_t j = i - T_B;
        float2 f = reinterpret_cast<const float2*>(attn_bias)[j];
        reinterpret_cast<__half2*>(abdst)[j] = __floats2half2_rn(f.x, f.y);
    }
}

// ---------------- LayerNorm: warp-per-row, 8 rows/block ----------------
__global__ __launch_bounds__(256) void ln_kernel(
    const float* __restrict__ in, const float* __restrict__ g, const float* __restrict__ b,
    __half* __restrict__ outH, float* __restrict__ outF)
{
    const int w = threadIdx.x >> 5, lane = threadIdx.x & 31;
    const int row = blockIdx.x * 8 + w;
    const float* x = in + (size_t)row * HH;

    float4 v[6];
    float s = 0.f, s2 = 0.f;
#pragma unroll
    for (int i = 0; i < 6; i++) {
        v[i] = *reinterpret_cast<const float4*>(x + lane * 4 + i * 128);
        s  += v[i].x + v[i].y + v[i].z + v[i].w;
        s2 += v[i].x * v[i].x + v[i].y * v[i].y + v[i].z * v[i].z + v[i].w * v[i].w;
    }
#pragma unroll
    for (int o = 16; o; o >>= 1) {
        s  += __shfl_xor_sync(0xffffffffu, s,  o);
        s2 += __shfl_xor_sync(0xffffffffu, s2, o);
    }
    const float mean = s * (1.f / HH);
    const float rstd = rsqrtf(s2 * (1.f / HH) - mean * mean + LN_EPS);

#pragma unroll
    for (int i = 0; i < 6; i++) {
        const int c = lane * 4 + i * 128;
        float o0 = (v[i].x - mean) * rstd * g[c]     + b[c];
        float o1 = (v[i].y - mean) * rstd * g[c + 1] + b[c + 1];
        float o2 = (v[i].z - mean) * rstd * g[c + 2] + b[c + 2];
        float o3 = (v[i].w - mean) * rstd * g[c + 3] + b[c + 3];
        if (outH) {
            __half2 p0 = __floats2half2_rn(o0, o1);
            __half2 p1 = __floats2half2_rn(o2, o3);
            uint2 pk = { *reinterpret_cast<uint32_t*>(&p0), *reinterpret_cast<uint32_t*>(&p1) };
            *reinterpret_cast<uint2*>(outH + (size_t)row * HH + c) = pk;
        } else {
            float4 ov = { o0, o1, o2, o3 };
            *reinterpret_cast<float4*>(outF + (size_t)row * HH + c) = ov;
        }
    }
}

// ---------------- asm helpers ----------------
__device__ __forceinline__ void cp16(void* smem, const void* gmem) {
    unsigned sa = (unsigned)__cvta_generic_to_shared(smem);
    asm volatile("cp.async.cg.shared.global [%0], [%1], 16;\n" :: "r"(sa), "l"(gmem));
}
__device__ __forceinline__ void cp_commit() { asm volatile("cp.async.commit_group;\n"); }
__device__ __forceinline__ unsigned smem_u32(const void* p) {
    return (unsigned)__cvta_generic_to_shared(p);
}
__device__ __forceinline__ uint32_t h2_as_u32(__half2 h) {
    return *reinterpret_cast<uint32_t*>(&h);
}
__device__ __forceinline__ void ldsm4(uint32_t& r0, uint32_t& r1, uint32_t& r2, uint32_t& r3,
                                      unsigned addr) {
    asm volatile("ldmatrix.sync.aligned.m8n8.x4.shared.b16 {%0,%1,%2,%3}, [%4];"
                 : "=r"(r0), "=r"(r1), "=r"(r2), "=r"(r3) : "r"(addr));
}
__device__ __forceinline__ void ldsm4t(uint32_t& r0, uint32_t& r1, uint32_t& r2, uint32_t& r3,
                                       unsigned addr) {
    asm volatile("ldmatrix.sync.aligned.m8n8.x4.trans.shared.b16 {%0,%1,%2,%3}, [%4];"
                 : "=r"(r0), "=r"(r1), "=r"(r2), "=r"(r3) : "r"(addr));
}
__device__ __forceinline__ void mma16816(float& d0, float& d1, float& d2, float& d3,
                                         uint32_t a0, uint32_t a1, uint32_t a2, uint32_t a3,
                                         uint32_t b0, uint32_t b1) {
    asm volatile(
        "mma.sync.aligned.m16n8k16.row.col.f32.f16.f16.f32 "
        "{%0,%1,%2,%3}, {%4,%5,%6,%7}, {%8,%9}, {%0,%1,%2,%3};"
        : "+f"(d0), "+f"(d1), "+f"(d2), "+f"(d3)
        : "r"(a0), "r"(a1), "r"(a2), "r"(a3), "r"(b0), "r"(b1));
}

// ---------------- flash attention (R12/R13 best-known) ----------------
__global__ __launch_bounds__(256, 2) void flash_kernel(
    const __half* __restrict__ qg, const __half* __restrict__ kg,
    const __half* __restrict__ vg, const __half* __restrict__ biasg,
    __half* __restrict__ outH)
{
    __shared__ __align__(16) __half Qs[128 * 64];
    __shared__ __align__(16) __half Ks[2][64 * 64];
    __shared__ __align__(16) __half Vs[2][64 * 64];

    const int t = threadIdx.x, w = t >> 5, lane = t & 31;
    const int z = blockIdx.y;
    const int b = z / NH_, hh = z - b * NH_;
    const int q0 = blockIdx.x * 128;

    const __half* Qg = qg + (size_t)z * SS * DD + (size_t)q0 * DD;
    const __half* Kg = kg + (size_t)z * SS * DD;
    const __half* Vg = vg + (size_t)z * SS * DD;
    const __half* Bg = biasg + (size_t)z * SS * SS + (size_t)q0 * SS;

    const unsigned sQ = smem_u32(Qs);
    const unsigned sK[2] = { smem_u32(Ks[0]), smem_u32(Ks[1]) };
    const unsigned sV[2] = { smem_u32(Vs[0]), smem_u32(Vs[1]) };

    auto loadQ = [&]() {
#pragma unroll
        for (int j = 0; j < 4; j++) {
            int idx = t + j * 256;
            int r = idx >> 3, c = idx & 7;
            cp16((char*)Qs + r * 128 + ((c ^ (r & 7)) << 4), Qg + (size_t)r * DD + c * 8);
        }
    };
    auto loadKV = [&](int s, int chunk) {
        const __half* kc = Kg + (size_t)chunk * 64 * DD;
        const __half* vc = Vg + (size_t)chunk * 64 * DD;
#pragma unroll
        for (int j = 0; j < 2; j++) {
            int idx = t + j * 256;
            int r = idx >> 3, c = idx & 7;
            cp16((char*)Ks[s] + r * 128 + ((c ^ (r & 7)) << 4), kc + (size_t)r * DD + c * 8);
        }
#pragma unroll
        for (int j = 0; j < 2; j++) {
            int idx = t + j * 256;
            int r = idx >> 3, c = idx & 7;
            cp16((char*)Vs[s] + r * 128 + ((c ^ (r & 7)) << 4), vc + (size_t)r * DD + c * 8);
        }
    };

    loadQ(); loadKV(0, 0); cp_commit();
    loadKV(1, 1); cp_commit();

    float m0 = -1e30f, m1 = -1e30f, l0 = 0.f, l1 = 0.f;
    float o[8][4];
#pragma unroll
    for (int i = 0; i < 8; i++)
#pragma unroll
        for (int k = 0; k < 4; k++) o[i][k] = 0.f;

    asm volatile("cp.async.wait_group 1;\n");
    __syncthreads();
    uint32_t aq[4][4];
    {
        const int qrow = w * 16 + (lane & 15);
#pragma unroll
        for (int ks = 0; ks < 4; ks++) {
            int kch = ks * 2 + (lane >> 4);
            ldsm4(aq[ks][0], aq[ks][1], aq[ks][2], aq[ks][3],
                  sQ + qrow * 128 + ((kch ^ (qrow & 7)) << 4));
        }
    }

    const int r0g = w * 16 + (lane >> 2);
    const int cb2 = (lane & 3) * 2;

    for (int ch = 0; ch < 8; ch++) {
        if (ch > 0) {
            if (ch < 7) { asm volatile("cp.async.wait_group 1;\n"); }
            else        { asm volatile("cp.async.wait_group 0;\n"); }
            __syncthreads();
        }
        const int s = ch & 1;

        float sc[8][4];
        {
            const __half* bp0 = Bg + (size_t)r0g * SS + ch * 64 + cb2;
            const __half* bp1 = bp0 + 8 * SS;
#pragma unroll
            for (int nj = 0; nj < 8; nj++) {
                float2 bv0 = __half22float2(*reinterpret_cast<const __half2*>(bp0 + nj * 8));
                float2 bv1 = __half22float2(*reinterpret_cast<const __half2*>(bp1 + nj * 8));
                sc[nj][0] = bv0.x; sc[nj][1] = bv0.y;
                sc[nj][2] = bv1.x; sc[nj][3] = bv1.y;
            }
        }

#pragma unroll
        for (int ks = 0; ks < 4; ks++) {
#pragma unroll
            for (int ng = 0; ng < 4; ng++) {
                int nrow = ng * 16 + (lane & 15);
                int kch = ks * 2 + (lane >> 4);
                uint32_t r0, r1, r2, r3;
                ldsm4(r0, r1, r2, r3, sK[s] + nrow * 128 + ((kch ^ (nrow & 7)) << 4));
                mma16816(sc[ng*2][0], sc[ng*2][1], sc[ng*2][2], sc[ng*2][3],
                         aq[ks][0], aq[ks][1], aq[ks][2], aq[ks][3], r0, r2);
                mma16816(sc[ng*2+1][0], sc[ng*2+1][1], sc[ng*2+1][2], sc[ng*2+1][3],
                         aq[ks][0], aq[ks][1], aq[ks][2], aq[ks][3], r1, r3);
            }
        }

        float rm0 = -1e30f, rm1 = -1e30f;
#pragma unroll
        for (int nj = 0; nj < 8; nj++) {
            rm0 = fmaxf(rm0, fmaxf(sc[nj][0], sc[nj][1]));
            rm1 = fmaxf(rm1, fmaxf(sc[nj][2], sc[nj][3]));
        }
        rm0 = fmaxf(rm0, __shfl_xor_sync(0xffffffffu, rm0, 1));
        rm0 = fmaxf(rm0, __shfl_xor_sync(0xffffffffu, rm0, 2));
        rm1 = fmaxf(rm1, __shfl_xor_sync(0xffffffffu, rm1, 1));
        rm1 = fmaxf(rm1, __shfl_xor_sync(0xffffffffu, rm1, 2));

        float nm0 = fmaxf(m0, rm0), nm1 = fmaxf(m1, rm1);
        float al0 = __expf(m0 - nm0), al1 = __expf(m1 - nm1);
        m0 = nm0; m1 = nm1;

        uint32_t h0[8], h1[8];
        float rs0 = 0.f, rs1 = 0.f;
#pragma unroll
        for (int nj = 0; nj < 8; nj++) {
            float e0 = __expf(sc[nj][0] - nm0);
            float e1 = __expf(sc[nj][1] - nm0);
            float e2 = __expf(sc[nj][2] - nm1);
            float e3 = __expf(sc[nj][3] - nm1);
            rs0 += e0 + e1; rs1 += e2 + e3;
            h0[nj] = h2_as_u32(__floats2half2_rn(e0, e1));
            h1[nj] = h2_as_u32(__floats2half2_rn(e2, e3));
        }
        rs0 += __shfl_xor_sync(0xffffffffu, rs0, 1);
        rs0 += __shfl_xor_sync(0xffffffffu, rs0, 2);
        rs1 += __shfl_xor_sync(0xffffffffu, rs1, 1);
        rs1 += __shfl_xor_sync(0xffffffffu, rs1, 2);
        l0 = l0 * al0 + rs0;
        l1 = l1 * al1 + rs1;
#pragma unroll
        for (int i = 0; i < 8; i++) {
            o[i][0] *= al0; o[i][1] *= al0;
            o[i][2] *= al1; o[i][3] *= al1;
        }

#pragma unroll
        for (int j = 0; j < 4; j++) {
#pragma unroll
            for (int pr = 0; pr < 4; pr++) {
                int kk = j * 16 + (lane & 15);
                int nch = pr * 2 + (lane >> 4);
                uint32_t r0, r1, r2, r3;
                ldsm4t(r0, r1, r2, r3, sV[s] + kk * 128 + ((nch ^ (kk & 7)) << 4));
                mma16816(o[pr*2][0], o[pr*2][1], o[pr*2][2], o[pr*2][3],
                         h0[2*j], h1[2*j], h0[2*j+1], h1[2*j+1], r0, r1);
                mma16816(o[pr*2+1][0], o[pr*2+1][1], o[pr*2+1][2], o[pr*2+1][3],
                         h0[2*j], h1[2*j], h0[2*j+1], h1[2*j+1], r2, r3);
            }
        }
        __syncthreads();
        if (ch + 2 < 8) { loadKV(s, ch + 2); cp_commit(); }
        else if (ch < 7) { cp_commit(); }
    }

    const float inv0 = 1.f / l0, inv1 = 1.f / l1;
    const int row0 = q0 + r0g;
    const int col0 = hh * DD + cb2;
    __half* o0 = outH + ((size_t)(b * SS) + row0) * HH + col0;
    __half* o1 = o0 + 8 * HH;
#pragma unroll
    for (int pj = 0; pj < 8; pj++) {
        *reinterpret_cast<__half2*>(o0 + pj * 8) = __floats2half2_rn(o[pj][0] * inv0, o[pj][1] * inv0);
        *reinterpret_cast<__half2*>(o1 + pj * 8) = __floats2half2_rn(o[pj][2] * inv1, o[pj][3] * inv1);
    }
}

// ---------------- mma.sync GEMM: 128x128 tile, BK=64, 8 warps, 3-stage (R13 best) ----------------
#define MG_STAGES 3
#define MG_ASTG   16384
#define MG_BSTG   16384
#define MG_DSM    98304

template<int EPI>
__global__ __launch_bounds__(256, 2) void mgemm_kernel(
    const __half* __restrict__ Ag, const __half* __restrict__ Bg,
    const float* __restrict__ bias,
    float* __restrict__ outF, __half* __restrict__ outH,
    int K, int N, float oscale)
{
    extern __shared__ __align__(16) char dyn[];
    const unsigned sb = smem_u32(dyn);
    float* stg = reinterpret_cast<float*>(dyn);

    const int t = threadIdx.x, w = t >> 5, lane = t & 31;
    const int wm = w >> 2, wn = w & 3;
    const __half* A = Ag + (size_t)blockIdx.y * 128 * K;
    const int n0 = blockIdx.x * 128;

    float d[4][4][4];
#pragma unroll
    for (int i = 0; i < 4; i++)
#pragma unroll
        for (int j = 0; j < 4; j++)
#pragma unroll
            for (int k = 0; k < 4; k++) d[i][j][k] = 0.f;

    auto load_tiles = [&](int s, int k0) {
        char* as = dyn + s * MG_ASTG;
        char* bs = dyn + MG_STAGES * MG_ASTG + s * MG_BSTG;
#pragma unroll
        for (int i = 0; i < 4; i++) {           // A: 128 x 64 halves
            int idx = t + i * 256;
            int r = idx >> 3, c = idx & 7;
            cp16(as + r * 128 + ((c ^ (r & 7)) << 4), A + (size_t)r * K + k0 + c * 8);
        }
#pragma unroll
        for (int i = 0; i < 4; i++) {           // B: 64 x 128 halves
            int idx = t + i * 256;
            int k = idx >> 4, c = idx & 15;
            cp16(bs + k * 256 + ((c ^ (k & 7)) << 4), Bg + (size_t)(k0 + k) * N + n0 + c * 8);
        }
    };

    const int nk = K >> 6;
    load_tiles(0, 0); cp_commit();
    if (nk > 1) load_tiles(1, 64);
    cp_commit();

    int s = 0;
    for (int kt = 0; kt < nk; kt++) {
        asm volatile("cp.async.wait_group 1;\n");
        __syncthreads();
        {
            int kn = kt + 2;
            if (kn < nk) {
                int sn = s + 2; if (sn >= MG_STAGES) sn -= MG_STAGES;
                load_tiles(sn, kn * 64);
            }
            cp_commit();
        }
        const unsigned abase = sb + s * MG_ASTG;
        const unsigned bbase = sb + MG_STAGES * MG_ASTG + s * MG_BSTG;

#pragma unroll
        for (int ks = 0; ks < 4; ks++) {
            uint32_t a[4][4], b[2][4];
#pragma unroll
            for (int mi = 0; mi < 4; mi++) {
                int row = wm * 64 + mi * 16 + (lane & 15);
                int kch = ks * 2 + (lane >> 4);
                ldsm4(a[mi][0], a[mi][1], a[mi][2], a[mi][3],
                      abase + row * 128 + ((kch ^ (row & 7)) << 4));
            }
#pragma unroll
            for (int pj = 0; pj < 2; pj++) {
                int kk = ks * 16 + (lane & 15);
                int nch = wn * 4 + pj * 2 + (lane >> 4);
                ldsm4t(b[pj][0], b[pj][1], b[pj][2], b[pj][3],
                       bbase + kk * 256 + ((nch ^ (kk & 7)) << 4));
            }
#pragma unroll
            for (int mi = 0; mi < 4; mi++)
#pragma unroll
                for (int nj = 0; nj < 4; nj++)
                    mma16816(d[mi][nj][0], d[mi][nj][1], d[mi][nj][2], d[mi][nj][3],
                             a[mi][0], a[mi][1], a[mi][2], a[mi][3],
                             b[nj >> 1][(nj & 1) * 2], b[nj >> 1][(nj & 1) * 2 + 1]);
        }
        if (++s == MG_STAGES) s = 0;
    }
    __syncthreads();

    // ---- staging (stride 129) ----
    const int qr = lane >> 2, qc = (lane & 3) * 2;
#pragma unroll
    for (int mi = 0; mi < 4; mi++) {
#pragma unroll
        for (int nj = 0; nj < 4; nj++) {
            int r0 = wm * 64 + mi * 16 + qr;
            int c0 = wn * 32 + nj * 8 + qc;
            stg[r0 * 129 + c0]           = d[mi][nj][0];
            stg[r0 * 129 + c0 + 1]       = d[mi][nj][1];
            stg[(r0 + 8) * 129 + c0]     = d[mi][nj][2];
            stg[(r0 + 8) * 129 + c0 + 1] = d[mi][nj][3];
        }
    }
    __syncthreads();

    const int gi0 = blockIdx.y * 128;
    const int gj0 = blockIdx.x * 128;

#pragma unroll
    for (int it = 0; it < 32; it++) {
        int idx = t + it * 256;
        int rr = idx >> 6;
        int c2 = (idx & 63) * 2;
        int gi = gi0 + rr, gj = gj0 + c2;
        float a0 = stg[rr * 129 + c2];
        float a1 = stg[rr * 129 + c2 + 1];

        if (EPI == 6) {
            int which = gj / HH;
            int col = gj - which * HH;
            float f = (which == 0) ? oscale : 1.f;
            float v0 = (a0 + bias[gj]) * f;
            float v1 = (a1 + bias[gj + 1]) * f;
            int bb = gi >> 9, ss2 = gi & 511, hhh = col >> 6, dd = col & 63;
            *reinterpret_cast<__half2*>(
                &outH[(size_t)which * QKV_STRIDE +
                      (((size_t)(bb * NH_ + hhh) * SS + ss2) << 6) + dd]) =
                __floats2half2_rn(v0, v1);
        } else if (EPI == 3) {
            float* dst = &outF[(size_t)gi * N + gj];
            float2 old = *reinterpret_cast<float2*>(dst);
            old.x += a0 + bias[gj];
            old.y += a1 + bias[gj + 1];
            *reinterpret_cast<float2*>(dst) = old;
        } else { // EPI == 4
            float x0 = a0 + bias[gj];
            float x1 = a1 + bias[gj + 1];
            float g0 = 0.5f * x0 * (1.f + erff(x0 * 0.70710678118654752f));
            float g1 = 0.5f * x1 * (1.f + erff(x1 * 0.70710678118654752f));
            *reinterpret_cast<__half2*>(&outH[(size_t)gi * N + gj]) =
                __floats2half2_rn(g0, g1);
        }
    }
}

// ---------------- host ----------------
extern "C" void kernel_launch(void* const* d_in, const int* in_sizes, int n_in,
                              void* d_out, int out_size)
{
    const float* x         = (const float*)d_in[0];
    const float* attn_bias = (const float*)d_in[1];
    const float* ln1_g = (const float*)d_in[2];
    const float* ln1_b = (const float*)d_in[3];
    const float* wq = (const float*)d_in[4];
    const float* bq = (const float*)d_in[5];
    const float* wk = (const float*)d_in[6];
    const float* bk = (const float*)d_in[7];
    const float* wv = (const float*)d_in[8];
    const float* bv = (const float*)d_in[9];
    const float* wo = (const float*)d_in[10];
    const float* bo = (const float*)d_in[11];
    const float* ln2_g = (const float*)d_in[12];
    const float* ln2_b = (const float*)d_in[13];
    const float* w1 = (const float*)d_in[14];
    const float* b1 = (const float*)d_in[15];
    const float* w2 = (const float*)d_in[16];
    const float* b2 = (const float*)d_in[17];
    const float* fln_g = (const float*)d_in[18];
    const float* fln_b = (const float*)d_in[19];
    float* out = (float*)d_out;

    void* pv_ = nullptr;
    cudaGetSymbolAddress(&pv_, g_h);      float*  p_h    = (float*)pv_;
    cudaGetSymbolAddress(&pv_, g_y);      __half* p_y    = (__half*)pv_;
    cudaGetSymbolAddress(&pv_, g_qkv);    __half* p_qkv  = (__half*)pv_;
    cudaGetSymbolAddress(&pv_, g_attn);   __half* p_attn = (__half*)pv_;
    cudaGetSymbolAddress(&pv_, g_ff);     __half* p_ff   = (__half*)pv_;
    cudaGetSymbolAddress(&pv_, g_bias16); __half* p_b16  = (__half*)pv_;
    cudaGetSymbolAddress(&pv_, g_w16);    __half* p_w16  = (__half*)pv_;
    cudaGetSymbolAddress(&pv_, g_bqkv);   float*  p_bqkv = (float*)pv_;

    __half* wqkv16 = p_w16 + OFF_QKV;
    __half* wo16   = p_w16 + OFF_WO;
    __half* w116   = p_w16 + OFF_W1;
    __half* w216   = p_w16 + OFF_W2;

    cudaFuncSetAttribute(mgemm_kernel<6>, cudaFuncAttributeMaxDynamicSharedMemorySize, MG_DSM);
    cudaFuncSetAttribute(mgemm_kernel<3>, cudaFuncAttributeMaxDynamicSharedMemorySize, MG_DSM);
    cudaFuncSetAttribute(mgemm_kernel<4>, cudaFuncAttributeMaxDynamicSharedMemorySize, MG_DSM);

    // single fused init launch
    {
        size_t total = T_AB;
        init_kernel<<<(unsigned)((total + 255) / 256), 256>>>(
            x, attn_bias, wq, wk, wv, wo, w1, w2, bq, bk, bv,
            p_h, p_w16, p_bqkv, p_b16);
    }

    const dim3 blk(256);
    const dim3 grid_qkv(NQKV / 128, MR / 128);          // 18 x 64
    const dim3 grid_proj(HH / 128, MR / 128);           // 6 x 64
    const dim3 grid_ff1(FF_ / 128, MR / 128);           // 24 x 64
    const dim3 grid_fa(SS / 128, BB * NH_);
    const unsigned ln_blocks = MR / 8;

    for (int l = 0; l < LL; l++) {
        ln_kernel<<<ln_blocks, blk>>>(p_h, ln1_g + l * HH, ln1_b + l * HH, p_y, nullptr);
        mgemm_kernel<6><<<grid_qkv, blk, MG_DSM>>>(p_y, wqkv16 + (size_t)l * HH * NQKV,
                                                   p_bqkv + (size_t)l * NQKV,
                                                   nullptr, p_qkv, HH, NQKV, SCALE_Q);
        flash_kernel<<<grid_fa, blk>>>(p_qkv, p_qkv + QKV_STRIDE, p_qkv + 2 * QKV_STRIDE,
                                       p_b16, p_attn);
        mgemm_kernel<3><<<grid_proj, blk, MG_DSM>>>(p_attn, wo16 + (size_t)l * HHxHH, bo + l * HH,
                                                    p_h, nullptr, HH, HH, 1.f);
        ln_kernel<<<ln_blocks, blk>>>(p_h, ln2_g + l * HH, ln2_b + l * HH, p_y, nullptr);
        mgemm_kernel<4><<<grid_ff1, blk, MG_DSM>>>(p_y, w116 + (size_t)l * HHxFF, b1 + l * FF_,
                                                   nullptr, p_ff, HH, FF_, 1.f);
        mgemm_kernel<3><<<grid_proj, blk, MG_DSM>>>(p_ff, w216 + (size_t)l * HHxFF, b2 + l * HH,
                                                    p_h, nullptr, FF_, HH, 1.f);
    }
    ln_kernel<<<ln_blocks, blk>>>(p_h, fln_g, fln_b, nullptr, out);
}

// round 17
// speedup vs baseline: 1.2604x; 1.0014x over previous
#include <cuda_runtime.h>
#include <cuda_fp16.h>
#include <cstdint>

// ---------------- problem constants ----------------
#define BB   16
#define SS   512
#define HH   768
#define NH_  12
#define DD   64
#define FF_  3072
#define LL   4
#define MR   (BB*SS)
#define SCALE_Q 0.125f
#define LN_EPS 1e-5f

#define HHxHH   (HH*HH)
#define HHxFF   (HH*FF_)
#define NQKV    (3*HH)                 // 2304
#define QKV_STRIDE ((size_t)MR*HH)
#define NBIAS   ((size_t)BB*NH_*SS*SS)

// ---------------- scratch ----------------
__device__ __align__(16) float  g_h[(size_t)MR*HH];
__device__ __align__(16) __half g_y[(size_t)MR*HH];
__device__ __align__(16) __half g_qkv[(size_t)3*MR*HH];      // q|k|v each [B,NH,S,D]
__device__ __align__(16) __half g_attn[(size_t)MR*HH];       // [B,S,H]
__device__ __align__(16) __half g_ff[(size_t)MR*FF_];
__device__ __align__(16) __half g_bias16[NBIAS];             // fp16 attn_bias
__device__ __align__(16) __half g_w16[(size_t)LL*(4*HHxHH + 2*HHxFF)];
__device__ __align__(16) float  g_bqkv[(size_t)LL*NQKV];

#define OFF_QKV ((size_t)0)
#define OFF_WO  ((size_t)3*LL*HHxHH)
#define OFF_W1  ((size_t)4*LL*HHxHH)
#define OFF_W2  ((size_t)4*LL*HHxHH + (size_t)LL*HHxFF)

// ---------------- single fused init kernel ----------------
#define NPAIRS ((size_t)LL*(4*HHxHH + 2*HHxFF)/2)
#define NCOPY4 ((size_t)MR*HH/4)
#define NBQKV  ((size_t)LL*NQKV)
#define NAB2   (NBIAS/2)
#define T_W    NPAIRS
#define T_H    (T_W + NCOPY4)
#define T_B    (T_H + NBQKV)
#define T_AB   (T_B + NAB2)

__global__ void init_kernel(
    const float* __restrict__ x,
    const float* __restrict__ attn_bias,
    const float* __restrict__ wq, const float* __restrict__ wk,
    const float* __restrict__ wv, const float* __restrict__ wo,
    const float* __restrict__ w1, const float* __restrict__ w2,
    const float* __restrict__ bq, const float* __restrict__ bk,
    const float* __restrict__ bv,
    float* __restrict__ h, __half* __restrict__ wdst,
    float* __restrict__ bdst, __half* __restrict__ abdst)
{
    size_t i = (size_t)blockIdx.x * blockDim.x + threadIdx.x;
    if (i < T_W) {
        const size_t NP = (size_t)LL * HHxHH / 2;
        const size_t NF = (size_t)LL * HHxFF / 2;
        const float* src; size_t off, dpi;
        if (i < 3 * NP) {
            size_t g = i / NP; off = i - g * NP;
            src = (g == 0) ? wq : (g == 1) ? wk : wv;
            size_t l  = off / (HHxHH / 2);
            size_t r  = off - l * (HHxHH / 2);
            size_t k  = r / (HH / 2);
            size_t nc = r - k * (HH / 2);
            dpi = l * ((size_t)HH * NQKV / 2) + k * (NQKV / 2) + g * (HH / 2) + nc;
        } else {
            dpi = i;
            if (i < 4 * NP) { src = wo; off = i - 3 * NP; }
            else {
                size_t j = i - 4 * NP;
                size_t g = j / NF; off = j - g * NF;
                src = g ? w2 : w1;
            }
        }
        float2 f = reinterpret_cast<const float2*>(src)[off];
        reinterpret_cast<__half2*>(wdst)[dpi] = __floats2half2_rn(f.x, f.y);
    } else if (i < T_H) {
        size_t j = i - T_W;
        reinterpret_cast<float4*>(h)[j] = reinterpret_cast<const float4*>(x)[j];
    } else if (i < T_B) {
        size_t j = i - T_H;
        int l = (int)(j / NQKV), n = (int)(j - (size_t)l * NQKV);
        float v = (n < HH) ? bq[l * HH + n]
                : (n < 2 * HH) ? bk[l * HH + n - HH]
                : bv[l * HH + n - 2 * HH];
        bdst[j] = v;
    } else if (i < T_AB) {
        size_t j = i - T_B;
        float2 f = reinterpret_cast<const float2*>(attn_bias)[j];
        reinterpret_cast<__half2*>(abdst)[j] = __floats2half2_rn(f.x, f.y);
    }
}

// ---------------- LayerNorm: warp-per-row, 8 rows/block ----------------
__global__ __launch_bounds__(256) void ln_kernel(
    const float* __restrict__ in, const float* __restrict__ g, const float* __restrict__ b,
    __half* __restrict__ outH, float* __restrict__ outF)
{
    const int w = threadIdx.x >> 5, lane = threadIdx.x & 31;
    const int row = blockIdx.x * 8 + w;
    const float* x = in + (size_t)row * HH;

    float4 v[6];
    float s = 0.f, s2 = 0.f;
#pragma unroll
    for (int i = 0; i < 6; i++) {
        v[i] = *reinterpret_cast<const float4*>(x + lane * 4 + i * 128);
        s  += v[i].x + v[i].y + v[i].z + v[i].w;
        s2 += v[i].x * v[i].x + v[i].y * v[i].y + v[i].z * v[i].z + v[i].w * v[i].w;
    }
#pragma unroll
    for (int o = 16; o; o >>= 1) {
        s  += __shfl_xor_sync(0xffffffffu, s,  o);
        s2 += __shfl_xor_sync(0xffffffffu, s2, o);
    }
    const float mean = s * (1.f / HH);
    const float rstd = rsqrtf(s2 * (1.f / HH) - mean * mean + LN_EPS);

#pragma unroll
    for (int i = 0; i < 6; i++) {
        const int c = lane * 4 + i * 128;
        float o0 = (v[i].x - mean) * rstd * g[c]     + b[c];
        float o1 = (v[i].y - mean) * rstd * g[c + 1] + b[c + 1];
        float o2 = (v[i].z - mean) * rstd * g[c + 2] + b[c + 2];
        float o3 = (v[i].w - mean) * rstd * g[c + 3] + b[c + 3];
        if (outH) {
            __half2 p0 = __floats2half2_rn(o0, o1);
            __half2 p1 = __floats2half2_rn(o2, o3);
            uint2 pk = { *reinterpret_cast<uint32_t*>(&p0), *reinterpret_cast<uint32_t*>(&p1) };
            *reinterpret_cast<uint2*>(outH + (size_t)row * HH + c) = pk;
        } else {
            float4 ov = { o0, o1, o2, o3 };
            *reinterpret_cast<float4*>(outF + (size_t)row * HH + c) = ov;
        }
    }
}

// ---------------- asm helpers ----------------
__device__ __forceinline__ void cp16(void* smem, const void* gmem) {
    unsigned sa = (unsigned)__cvta_generic_to_shared(smem);
    asm volatile("cp.async.cg.shared.global [%0], [%1], 16;\n" :: "r"(sa), "l"(gmem));
}
__device__ __forceinline__ void cp_commit() { asm volatile("cp.async.commit_group;\n"); }
__device__ __forceinline__ unsigned smem_u32(const void* p) {
    return (unsigned)__cvta_generic_to_shared(p);
}
__device__ __forceinline__ uint32_t h2_as_u32(__half2 h) {
    return *reinterpret_cast<uint32_t*>(&h);
}
__device__ __forceinline__ void ldsm4(uint32_t& r0, uint32_t& r1, uint32_t& r2, uint32_t& r3,
                                      unsigned addr) {
    asm volatile("ldmatrix.sync.aligned.m8n8.x4.shared.b16 {%0,%1,%2,%3}, [%4];"
                 : "=r"(r0), "=r"(r1), "=r"(r2), "=r"(r3) : "r"(addr));
}
__device__ __forceinline__ void ldsm4t(uint32_t& r0, uint32_t& r1, uint32_t& r2, uint32_t& r3,
                                       unsigned addr) {
    asm volatile("ldmatrix.sync.aligned.m8n8.x4.trans.shared.b16 {%0,%1,%2,%3}, [%4];"
                 : "=r"(r0), "=r"(r1), "=r"(r2), "=r"(r3) : "r"(addr));
}
__device__ __forceinline__ void mma16816(float& d0, float& d1, float& d2, float& d3,
                                         uint32_t a0, uint32_t a1, uint32_t a2, uint32_t a3,
                                         uint32_t b0, uint32_t b1) {
    asm volatile(
        "mma.sync.aligned.m16n8k16.row.col.f32.f16.f16.f32 "
        "{%0,%1,%2,%3}, {%4,%5,%6,%7}, {%8,%9}, {%0,%1,%2,%3};"
        : "+f"(d0), "+f"(d1), "+f"(d2), "+f"(d3)
        : "r"(a0), "r"(a1), "r"(a2), "r"(a3), "r"(b0), "r"(b1));
}

// ---------------- flash attention: bias prefetched via cp.async (dyn smem) ----------------
// layout (bytes): Q 0..16384 | K0 16384 | K1 24576 | V0 32768 | V1 40960 | B0 49152 | B1 67584
// bias buffer: 128 rows x 64 halves, row stride 144B (16B-aligned, 8-row bank spread)
#define FL_Q   0
#define FL_K0  16384
#define FL_V0  32768
#define FL_B0  49152
#define FL_BST 144
#define FL_BSZ 18432
#define FL_DSM 86016

__global__ __launch_bounds__(256, 2) void flash_kernel(
    const __half* __restrict__ qg, const __half* __restrict__ kg,
    const __half* __restrict__ vg, const __half* __restrict__ biasg,
    __half* __restrict__ outH)
{
    extern __shared__ __align__(16) char dyn[];
    const unsigned sb = smem_u32(dyn);

    const int t = threadIdx.x, w = t >> 5, lane = t & 31;
    const int z = blockIdx.y;
    const int b = z / NH_, hh = z - b * NH_;
    const int q0 = blockIdx.x * 128;

    const __half* Qg = qg + (size_t)z * SS * DD + (size_t)q0 * DD;
    const __half* Kg = kg + (size_t)z * SS * DD;
    const __half* Vg = vg + (size_t)z * SS * DD;
    const __half* Bg = biasg + (size_t)z * SS * SS + (size_t)q0 * SS;

    const unsigned sQ = sb + FL_Q;
    const unsigned sK[2] = { sb + FL_K0, sb + FL_K0 + 8192 };
    const unsigned sV[2] = { sb + FL_V0, sb + FL_V0 + 8192 };
    char* const  pB[2] = { dyn + FL_B0, dyn + FL_B0 + FL_BSZ };

    auto loadQ = [&]() {
#pragma unroll
        for (int j = 0; j < 4; j++) {
            int idx = t + j * 256;
            int r = idx >> 3, c = idx & 7;
            cp16(dyn + FL_Q + r * 128 + ((c ^ (r & 7)) << 4), Qg + (size_t)r * DD + c * 8);
        }
    };
    auto loadKV = [&](int s, int chunk) {
        const __half* kc = Kg + (size_t)chunk * 64 * DD;
        const __half* vc = Vg + (size_t)chunk * 64 * DD;
        char* ks = dyn + FL_K0 + s * 8192;
        char* vs = dyn + FL_V0 + s * 8192;
#pragma unroll
        for (int j = 0; j < 2; j++) {
            int idx = t + j * 256;
            int r = idx >> 3, c = idx & 7;
            cp16(ks + r * 128 + ((c ^ (r & 7)) << 4), kc + (size_t)r * DD + c * 8);
        }
#pragma unroll
        for (int j = 0; j < 2; j++) {
            int idx = t + j * 256;
            int r = idx >> 3, c = idx & 7;
            cp16(vs + r * 128 + ((c ^ (r & 7)) << 4), vc + (size_t)r * DD + c * 8);
        }
        // bias chunk: 128 rows x 64 halves (cols chunk*64..+64), 1024 cp16
        const __half* bc = Bg + (size_t)chunk * 64;
#pragma unroll
        for (int j = 0; j < 4; j++) {
            int idx = t + j * 256;
            int r = idx >> 3, c = idx & 7;
            cp16(pB[s] + r * FL_BST + c * 16, bc + (size_t)r * SS + c * 8);
        }
    };

    loadQ(); loadKV(0, 0); cp_commit();
    loadKV(1, 1); cp_commit();

    float m0 = -1e30f, m1 = -1e30f, l0 = 0.f, l1 = 0.f;
    float o[8][4];
#pragma unroll
    for (int i = 0; i < 8; i++)
#pragma unroll
        for (int k = 0; k < 4; k++) o[i][k] = 0.f;

    asm volatile("cp.async.wait_group 1;\n");
    __syncthreads();
    uint32_t aq[4][4];
    {
        const int qrow = w * 16 + (lane & 15);
#pragma unroll
        for (int ks = 0; ks < 4; ks++) {
            int kch = ks * 2 + (lane >> 4);
            ldsm4(aq[ks][0], aq[ks][1], aq[ks][2], aq[ks][3],
                  sQ + qrow * 128 + ((kch ^ (qrow & 7)) << 4));
        }
    }

    const int r0g = w * 16 + (lane >> 2);
    const int cb2 = (lane & 3) * 2;

    for (int ch = 0; ch < 8; ch++) {
        if (ch > 0) {
            if (ch < 7) { asm volatile("cp.async.wait_group 1;\n"); }
            else        { asm volatile("cp.async.wait_group 0;\n"); }
            __syncthreads();
        }
        const int s = ch & 1;

        // ---- S accumulator initialized with bias from smem ----
        float sc[8][4];
        {
            const char* bp0 = pB[s] + r0g * FL_BST + cb2 * 2;
            const char* bp1 = bp0 + 8 * FL_BST;
#pragma unroll
            for (int nj = 0; nj < 8; nj++) {
                float2 bv0 = __half22float2(*reinterpret_cast<const __half2*>(bp0 + nj * 16));
                float2 bv1 = __half22float2(*reinterpret_cast<const __half2*>(bp1 + nj * 16));
                sc[nj][0] = bv0.x; sc[nj][1] = bv0.y;
                sc[nj][2] = bv1.x; sc[nj][3] = bv1.y;
            }
        }

#pragma unroll
        for (int ks = 0; ks < 4; ks++) {
#pragma unroll
            for (int ng = 0; ng < 4; ng++) {
                int nrow = ng * 16 + (lane & 15);
                int kch = ks * 2 + (lane >> 4);
                uint32_t r0, r1, r2, r3;
                ldsm4(r0, r1, r2, r3, sK[s] + nrow * 128 + ((kch ^ (nrow & 7)) << 4));
                mma16816(sc[ng*2][0], sc[ng*2][1], sc[ng*2][2], sc[ng*2][3],
                         aq[ks][0], aq[ks][1], aq[ks][2], aq[ks][3], r0, r2);
                mma16816(sc[ng*2+1][0], sc[ng*2+1][1], sc[ng*2+1][2], sc[ng*2+1][3],
                         aq[ks][0], aq[ks][1], aq[ks][2], aq[ks][3], r1, r3);
            }
        }

        float rm0 = -1e30f, rm1 = -1e30f;
#pragma unroll
        for (int nj = 0; nj < 8; nj++) {
            rm0 = fmaxf(rm0, fmaxf(sc[nj][0], sc[nj][1]));
            rm1 = fmaxf(rm1, fmaxf(sc[nj][2], sc[nj][3]));
        }
        rm0 = fmaxf(rm0, __shfl_xor_sync(0xffffffffu, rm0, 1));
        rm0 = fmaxf(rm0, __shfl_xor_sync(0xffffffffu, rm0, 2));
        rm1 = fmaxf(rm1, __shfl_xor_sync(0xffffffffu, rm1, 1));
        rm1 = fmaxf(rm1, __shfl_xor_sync(0xffffffffu, rm1, 2));

        float nm0 = fmaxf(m0, rm0), nm1 = fmaxf(m1, rm1);
        float al0 = __expf(m0 - nm0), al1 = __expf(m1 - nm1);
        m0 = nm0; m1 = nm1;

        uint32_t h0[8], h1[8];
        float rs0 = 0.f, rs1 = 0.f;
#pragma unroll
        for (int nj = 0; nj < 8; nj++) {
            float e0 = __expf(sc[nj][0] - nm0);
            float e1 = __expf(sc[nj][1] - nm0);
            float e2 = __expf(sc[nj][2] - nm1);
            float e3 = __expf(sc[nj][3] - nm1);
            rs0 += e0 + e1; rs1 += e2 + e3;
            h0[nj] = h2_as_u32(__floats2half2_rn(e0, e1));
            h1[nj] = h2_as_u32(__floats2half2_rn(e2, e3));
        }
        rs0 += __shfl_xor_sync(0xffffffffu, rs0, 1);
        rs0 += __shfl_xor_sync(0xffffffffu, rs0, 2);
        rs1 += __shfl_xor_sync(0xffffffffu, rs1, 1);
        rs1 += __shfl_xor_sync(0xffffffffu, rs1, 2);
        l0 = l0 * al0 + rs0;
        l1 = l1 * al1 + rs1;
#pragma unroll
        for (int i = 0; i < 8; i++) {
            o[i][0] *= al0; o[i][1] *= al0;
            o[i][2] *= al1; o[i][3] *= al1;
        }

#pragma unroll
        for (int j = 0; j < 4; j++) {
#pragma unroll
            for (int pr = 0; pr < 4; pr++) {
                int kk = j * 16 + (lane & 15);
                int nch = pr * 2 + (lane >> 4);
                uint32_t r0, r1, r2, r3;
                ldsm4t(r0, r1, r2, r3, sV[s] + kk * 128 + ((nch ^ (kk & 7)) << 4));
                mma16816(o[pr*2][0], o[pr*2][1], o[pr*2][2], o[pr*2][3],
                         h0[2*j], h1[2*j], h0[2*j+1], h1[2*j+1], r0, r1);
                mma16816(o[pr*2+1][0], o[pr*2+1][1], o[pr*2+1][2], o[pr*2+1][3],
                         h0[2*j], h1[2*j], h0[2*j+1], h1[2*j+1], r2, r3);
            }
        }
        __syncthreads();
        if (ch + 2 < 8) { loadKV(s, ch + 2); cp_commit(); }
        else if (ch < 7) { cp_commit(); }
    }

    const float inv0 = 1.f / l0, inv1 = 1.f / l1;
    const int row0 = q0 + r0g;
    const int col0 = hh * DD + cb2;
    __half* o0 = outH + ((size_t)(b * SS) + row0) * HH + col0;
    __half* o1 = o0 + 8 * HH;
#pragma unroll
    for (int pj = 0; pj < 8; pj++) {
        *reinterpret_cast<__half2*>(o0 + pj * 8) = __floats2half2_rn(o[pj][0] * inv0, o[pj][1] * inv0);
        *reinterpret_cast<__half2*>(o1 + pj * 8) = __floats2half2_rn(o[pj][2] * inv1, o[pj][3] * inv1);
    }
}

// ---------------- mma.sync GEMM: 128x128 tile, BK=64, 8 warps, 3-stage (R13 best) ----------------
#define MG_STAGES 3
#define MG_ASTG   16384
#define MG_BSTG   16384
#define MG_DSM    98304

template<int EPI>
__global__ __launch_bounds__(256, 2) void mgemm_kernel(
    const __half* __restrict__ Ag, const __half* __restrict__ Bg,
    const float* __restrict__ bias,
    float* __restrict__ outF, __half* __restrict__ outH,
    int K, int N, float oscale)
{
    extern __shared__ __align__(16) char dyn[];
    const unsigned sb = smem_u32(dyn);
    float* stg = reinterpret_cast<float*>(dyn);

    const int t = threadIdx.x, w = t >> 5, lane = t & 31;
    const int wm = w >> 2, wn = w & 3;
    const __half* A = Ag + (size_t)blockIdx.y * 128 * K;
    const int n0 = blockIdx.x * 128;

    float d[4][4][4];
#pragma unroll
    for (int i = 0; i < 4; i++)
#pragma unroll
        for (int j = 0; j < 4; j++)
#pragma unroll
            for (int k = 0; k < 4; k++) d[i][j][k] = 0.f;

    auto load_tiles = [&](int s, int k0) {
        char* as = dyn + s * MG_ASTG;
        char* bs = dyn + MG_STAGES * MG_ASTG + s * MG_BSTG;
#pragma unroll
        for (int i = 0; i < 4; i++) {
            int idx = t + i * 256;
            int r = idx >> 3, c = idx & 7;
            cp16(as + r * 128 + ((c ^ (r & 7)) << 4), A + (size_t)r * K + k0 + c * 8);
        }
#pragma unroll
        for (int i = 0; i < 4; i++) {
            int idx = t + i * 256;
            int k = idx >> 4, c = idx & 15;
            cp16(bs + k * 256 + ((c ^ (k & 7)) << 4), Bg + (size_t)(k0 + k) * N + n0 + c * 8);
        }
    };

    const int nk = K >> 6;
    load_tiles(0, 0); cp_commit();
    if (nk > 1) load_tiles(1, 64);
    cp_commit();

    int s = 0;
    for (int kt = 0; kt < nk; kt++) {
        asm volatile("cp.async.wait_group 1;\n");
        __syncthreads();
        {
            int kn = kt + 2;
            if (kn < nk) {
                int sn = s + 2; if (sn >= MG_STAGES) sn -= MG_STAGES;
                load_tiles(sn, kn * 64);
            }
            cp_commit();
        }
        const unsigned abase = sb + s * MG_ASTG;
        const unsigned bbase = sb + MG_STAGES * MG_ASTG + s * MG_BSTG;

#pragma unroll
        for (int ks = 0; ks < 4; ks++) {
            uint32_t a[4][4], b[2][4];
#pragma unroll
            for (int mi = 0; mi < 4; mi++) {
                int row = wm * 64 + mi * 16 + (lane & 15);
                int kch = ks * 2 + (lane >> 4);
                ldsm4(a[mi][0], a[mi][1], a[mi][2], a[mi][3],
                      abase + row * 128 + ((kch ^ (row & 7)) << 4));
            }
#pragma unroll
            for (int pj = 0; pj < 2; pj++) {
                int kk = ks * 16 + (lane & 15);
                int nch = wn * 4 + pj * 2 + (lane >> 4);
                ldsm4t(b[pj][0], b[pj][1], b[pj][2], b[pj][3],
                       bbase + kk * 256 + ((nch ^ (kk & 7)) << 4));
            }
#pragma unroll
            for (int mi = 0; mi < 4; mi++)
#pragma unroll
                for (int nj = 0; nj < 4; nj++)
                    mma16816(d[mi][nj][0], d[mi][nj][1], d[mi][nj][2], d[mi][nj][3],
                             a[mi][0], a[mi][1], a[mi][2], a[mi][3],
                             b[nj >> 1][(nj & 1) * 2], b[nj >> 1][(nj & 1) * 2 + 1]);
        }
        if (++s == MG_STAGES) s = 0;
    }
    __syncthreads();

    const int qr = lane >> 2, qc = (lane & 3) * 2;
#pragma unroll
    for (int mi = 0; mi < 4; mi++) {
#pragma unroll
        for (int nj = 0; nj < 4; nj++) {
            int r0 = wm * 64 + mi * 16 + qr;
            int c0 = wn * 32 + nj * 8 + qc;
            stg[r0 * 129 + c0]           = d[mi][nj][0];
            stg[r0 * 129 + c0 + 1]       = d[mi][nj][1];
            stg[(r0 + 8) * 129 + c0]     = d[mi][nj][2];
            stg[(r0 + 8) * 129 + c0 + 1] = d[mi][nj][3];
        }
    }
    __syncthreads();

    const int gi0 = blockIdx.y * 128;
    const int gj0 = blockIdx.x * 128;

#pragma unroll
    for (int it = 0; it < 32; it++) {
        int idx = t + it * 256;
        int rr = idx >> 6;
        int c2 = (idx & 63) * 2;
        int gi = gi0 + rr, gj = gj0 + c2;
        float a0 = stg[rr * 129 + c2];
        float a1 = stg[rr * 129 + c2 + 1];

        if (EPI == 6) {
            int which = gj / HH;
            int col = gj - which * HH;
            float f = (which == 0) ? oscale : 1.f;
            float v0 = (a0 + bias[gj]) * f;
            float v1 = (a1 + bias[gj + 1]) * f;
            int bb = gi >> 9, ss2 = gi & 511, hhh = col >> 6, dd = col & 63;
            *reinterpret_cast<__half2*>(
                &outH[(size_t)which * QKV_STRIDE +
                      (((size_t)(bb * NH_ + hhh) * SS + ss2) << 6) + dd]) =
                __floats2half2_rn(v0, v1);
        } else if (EPI == 3) {
            float* dst = &outF[(size_t)gi * N + gj];
            float2 old = *reinterpret_cast<float2*>(dst);
            old.x += a0 + bias[gj];
            old.y += a1 + bias[gj + 1];
            *reinterpret_cast<float2*>(dst) = old;
        } else { // EPI == 4
            float x0 = a0 + bias[gj];
            float x1 = a1 + bias[gj + 1];
            float g0 = 0.5f * x0 * (1.f + erff(x0 * 0.70710678118654752f));
            float g1 = 0.5f * x1 * (1.f + erff(x1 * 0.70710678118654752f));
            *reinterpret_cast<__half2*>(&outH[(size_t)gi * N + gj]) =
                __floats2half2_rn(g0, g1);
        }
    }
}

// ---------------- host ----------------
extern "C" void kernel_launch(void* const* d_in, const int* in_sizes, int n_in,
                              void* d_out, int out_size)
{
    const float* x         = (const float*)d_in[0];
    const float* attn_bias = (const float*)d_in[1];
    const float* ln1_g = (const float*)d_in[2];
    const float* ln1_b = (const float*)d_in[3];
    const float* wq = (const float*)d_in[4];
    const float* bq = (const float*)d_in[5];
    const float* wk = (const float*)d_in[6];
    const float* bk = (const float*)d_in[7];
    const float* wv = (const float*)d_in[8];
    const float* bv = (const float*)d_in[9];
    const float* wo = (const float*)d_in[10];
    const float* bo = (const float*)d_in[11];
    const float* ln2_g = (const float*)d_in[12];
    const float* ln2_b = (const float*)d_in[13];
    const float* w1 = (const float*)d_in[14];
    const float* b1 = (const float*)d_in[15];
    const float* w2 = (const float*)d_in[16];
    const float* b2 = (const float*)d_in[17];
    const float* fln_g = (const float*)d_in[18];
    const float* fln_b = (const float*)d_in[19];
    float* out = (float*)d_out;

    void* pv_ = nullptr;
    cudaGetSymbolAddress(&pv_, g_h);      float*  p_h    = (float*)pv_;
    cudaGetSymbolAddress(&pv_, g_y);      __half* p_y    = (__half*)pv_;
    cudaGetSymbolAddress(&pv_, g_qkv);    __half* p_qkv  = (__half*)pv_;
    cudaGetSymbolAddress(&pv_, g_attn);   __half* p_attn = (__half*)pv_;
    cudaGetSymbolAddress(&pv_, g_ff);     __half* p_ff   = (__half*)pv_;
    cudaGetSymbolAddress(&pv_, g_bias16); __half* p_b16  = (__half*)pv_;
    cudaGetSymbolAddress(&pv_, g_w16);    __half* p_w16  = (__half*)pv_;
    cudaGetSymbolAddress(&pv_, g_bqkv);   float*  p_bqkv = (float*)pv_;

    __half* wqkv16 = p_w16 + OFF_QKV;
    __half* wo16   = p_w16 + OFF_WO;
    __half* w116   = p_w16 + OFF_W1;
    __half* w216   = p_w16 + OFF_W2;

    cudaFuncSetAttribute(mgemm_kernel<6>, cudaFuncAttributeMaxDynamicSharedMemorySize, MG_DSM);
    cudaFuncSetAttribute(mgemm_kernel<3>, cudaFuncAttributeMaxDynamicSharedMemorySize, MG_DSM);
    cudaFuncSetAttribute(mgemm_kernel<4>, cudaFuncAttributeMaxDynamicSharedMemorySize, MG_DSM);
    cudaFuncSetAttribute(flash_kernel,    cudaFuncAttributeMaxDynamicSharedMemorySize, FL_DSM);

    // single fused init launch
    {
        size_t total = T_AB;
        init_kernel<<<(unsigned)((total + 255) / 256), 256>>>(
            x, attn_bias, wq, wk, wv, wo, w1, w2, bq, bk, bv,
            p_h, p_w16, p_bqkv, p_b16);
    }

    const dim3 blk(256);
    const dim3 grid_qkv(NQKV / 128, MR / 128);
    const dim3 grid_proj(HH / 128, MR / 128);
    const dim3 grid_ff1(FF_ / 128, MR / 128);
    const dim3 grid_fa(SS / 128, BB * NH_);
    const unsigned ln_blocks = MR / 8;

    for (int l = 0; l < LL; l++) {
        ln_kernel<<<ln_blocks, blk>>>(p_h, ln1_g + l * HH, ln1_b + l * HH, p_y, nullptr);
        mgemm_kernel<6><<<grid_qkv, blk, MG_DSM>>>(p_y, wqkv16 + (size_t)l * HH * NQKV,
                                                   p_bqkv + (size_t)l * NQKV,
                                                   nullptr, p_qkv, HH, NQKV, SCALE_Q);
        flash_kernel<<<grid_fa, blk, FL_DSM>>>(p_qkv, p_qkv + QKV_STRIDE, p_qkv + 2 * QKV_STRIDE,
                                               p_b16, p_attn);
        mgemm_kernel<3><<<grid_proj, blk, MG_DSM>>>(p_attn, wo16 + (size_t)l * HHxHH, bo + l * HH,
                                                    p_h, nullptr, HH, HH, 1.f);
        ln_kernel<<<ln_blocks, blk>>>(p_h, ln2_g + l * HH, ln2_b + l * HH, p_y, nullptr);
        mgemm_kernel<4><<<grid_ff1, blk, MG_DSM>>>(p_y, w116 + (size_t)l * HHxFF, b1 + l * FF_,
                                                   nullptr, p_ff, HH, FF_, 1.f);
        mgemm_kernel<3><<<grid_proj, blk, MG_DSM>>>(p_ff, w216 + (size_t)l * HHxFF, b2 + l * HH,
                                                    p_h, nullptr, FF_, HH, 1.f);
    }
    ln_kernel<<<ln_blocks, blk>>>(p_h, fln_g, fln_b, nullptr, out);
}